// round 6
// baseline (speedup 1.0000x reference)
#include <cuda_runtime.h>
#include <cstdint>

#define IN_FEAT 3072
#define PADDED  4096
#define M_ROWS  8192
#define N_COLS  4096
#define K_DIM   4096

#define BM 128
#define BNT 128              // tensor columns per tile
#define BND 64               // dp4a columns per tile
#define BN (BNT + BND)       // 192
#define BK 64
#define NSTAGE 4
#define NITER (K_DIM / BK)

#define A_STAGE 8192                       // 128 rows x 64 B
#define B_STAGE (BN * BK)                  // 192 rows x 64 B = 12288
#define SMEM_B_OFF (NSTAGE * A_STAGE)      // 32768
#define SMEM_TOTAL (NSTAGE * (A_STAGE + B_STAGE))   // 81920

// -------- device scratch (static globals: no allocations allowed) ----------
__device__ int8_t g_zx[(size_t)M_ROWS * K_DIM];   // 32 MB
__device__ int8_t g_zw[(size_t)N_COLS * K_DIM];   // 16 MB
__device__ float  g_alpha[M_ROWS];
__device__ float  g_beta[N_COLS];

// -------- helpers -----------------------------------------------------------
__device__ __forceinline__ uint32_t smem_u32(const void* p) {
    uint32_t a;
    asm("{ .reg .u64 t; cvta.to.shared.u64 t, %1; cvt.u32.u64 %0, t; }"
        : "=r"(a) : "l"(p));
    return a;
}

__device__ __forceinline__ void cpa16(uint32_t sdst, const void* gsrc) {
    asm volatile("cp.async.cg.shared.global [%0], [%1], 16;" :: "r"(sdst), "l"(gsrc));
}

__device__ __forceinline__ void ldm4(uint32_t addr, uint32_t& r0, uint32_t& r1,
                                     uint32_t& r2, uint32_t& r3) {
    asm volatile("ldmatrix.sync.aligned.m8n8.x4.shared.b16 {%0,%1,%2,%3}, [%4];"
                 : "=r"(r0), "=r"(r1), "=r"(r2), "=r"(r3) : "r"(addr));
}

__device__ __forceinline__ void mma_s8(int* d, const uint32_t* a, uint32_t b0, uint32_t b1) {
    asm volatile(
        "mma.sync.aligned.m16n8k32.row.col.s32.s8.s8.s32 "
        "{%0,%1,%2,%3}, {%4,%5,%6,%7}, {%8,%9}, {%0,%1,%2,%3};"
        : "+r"(d[0]), "+r"(d[1]), "+r"(d[2]), "+r"(d[3])
        : "r"(a[0]), "r"(a[1]), "r"(a[2]), "r"(a[3]), "r"(b0), "r"(b1));
}

__device__ __forceinline__ uint4 lds128(uint32_t addr) {
    uint4 v;
    asm volatile("ld.shared.v4.u32 {%0,%1,%2,%3}, [%4];"
                 : "=r"(v.x), "=r"(v.y), "=r"(v.z), "=r"(v.w) : "r"(addr));
    return v;
}

__device__ __forceinline__ int dp4a_s(uint32_t a, uint32_t b, int c) {
    int d;
    asm("dp4a.s32.s32 %0, %1, %2, %3;" : "=r"(d) : "r"(a), "r"(b), "r"(c));
    return d;
}

// swizzle for 64-byte rows at 16B granules (cp.async-store / ldmatrix / LDS.128 safe)
#define SWZ64(row, c) (((uint32_t)(row) << 6) + ((((c) ^ (((row) >> 1) & 3)) & 3) << 4))

// ============================================================================
// Kernel 1: per-row pad -> FWHT(4096) -> quantize (z = q-128, int8) -> row sum
// ============================================================================
__global__ void __launch_bounds__(256)
hq_fwht_quant(const float* __restrict__ x, const float* __restrict__ w,
              const float* __restrict__ bias, float kA, float c2) {
    __shared__ float xch[PADDED];
    __shared__ float wsum[8];

    int row = blockIdx.x;
    int mode = (row >= M_ROWS);
    if (mode) row -= M_ROWS;
    const float* in = mode ? (w + (size_t)row * IN_FEAT) : (x + (size_t)row * IN_FEAT);
    const int t = threadIdx.x;

    float v[16];
    if (t < IN_FEAT / 16) {
        const float4* p = (const float4*)(in + t * 16);
        float4 a0 = p[0], a1 = p[1], a2 = p[2], a3 = p[3];
        v[0]=a0.x; v[1]=a0.y; v[2]=a0.z; v[3]=a0.w;
        v[4]=a1.x; v[5]=a1.y; v[6]=a1.z; v[7]=a1.w;
        v[8]=a2.x; v[9]=a2.y; v[10]=a2.z; v[11]=a2.w;
        v[12]=a3.x; v[13]=a3.y; v[14]=a3.z; v[15]=a3.w;
    } else {
        #pragma unroll
        for (int e = 0; e < 16; ++e) v[e] = 0.0f;
    }

    #pragma unroll
    for (int st = 1; st < 16; st <<= 1) {
        #pragma unroll
        for (int e = 0; e < 16; ++e)
            if (!(e & st)) {
                float a = v[e], b = v[e | st];
                v[e] = a + b;
                v[e | st] = a - b;
            }
    }
    #pragma unroll
    for (int b = 1; b <= 16; b <<= 1) {
        bool up = (t & b) != 0;
        #pragma unroll
        for (int e = 0; e < 16; ++e) {
            float o = __shfl_xor_sync(0xffffffffu, v[e], b, 32);
            v[e] = up ? (o - v[e]) : (v[e] + o);
        }
    }
    #pragma unroll
    for (int b = 32; b <= 128; b <<= 1) {
        __syncthreads();
        #pragma unroll
        for (int e = 0; e < 16; ++e) xch[e * 256 + t] = v[e];
        __syncthreads();
        int pt = t ^ b;
        bool up = (t & b) != 0;
        #pragma unroll
        for (int e = 0; e < 16; ++e) {
            float o = xch[e * 256 + pt];
            v[e] = up ? (o - v[e]) : (v[e] + o);
        }
    }

    const float inv_qs = 255.0f / 768.0f;
    int zi[16];
    float zsum = 0.0f;
    #pragma unroll
    for (int e = 0; e < 16; ++e) {
        float u = fminf(fmaxf(v[e], -384.0f), 384.0f);
        float q = fminf(fmaxf(rintf((u + 384.0f) * inv_qs), 0.0f), 255.0f);
        zi[e] = (int)q - 128;
        zsum += (float)zi[e];
    }
    uint32_t pk[4];
    #pragma unroll
    for (int j = 0; j < 4; ++j)
        pk[j] = (uint32_t)(zi[4*j] & 0xff) | ((uint32_t)(zi[4*j+1] & 0xff) << 8) |
                ((uint32_t)(zi[4*j+2] & 0xff) << 16) | ((uint32_t)(zi[4*j+3] & 0xff) << 24);
    int8_t* oz = (mode ? g_zw : g_zx) + (size_t)row * PADDED + t * 16;
    *(uint4*)oz = make_uint4(pk[0], pk[1], pk[2], pk[3]);

    #pragma unroll
    for (int off = 16; off > 0; off >>= 1)
        zsum += __shfl_down_sync(0xffffffffu, zsum, off, 32);
    if ((t & 31) == 0) wsum[t >> 5] = zsum;
    __syncthreads();
    if (t == 0) {
        float S = 0.0f;
        #pragma unroll
        for (int i = 0; i < 8; ++i) S += wsum[i];
        float stat = kA * S;
        if (mode) g_beta[row] = stat + c2 + bias[row];
        else      g_alpha[row] = stat;
    }
}

// ============================================================================
// Kernel 2: hybrid GEMM. Tile 128 x 192: cols 0..127 via mma.sync (tensor
// pipe), cols 128..191 via dp4a (fma pipe). Same 8 warps issue both -> both
// pipes busy on every SM. 1 CTA/SM, 4-stage cp.async.
// ============================================================================
__device__ __forceinline__ void load_chunk(uint32_t sb, const int8_t* Ag, const int8_t* Bg,
                                           int k0, int s, int tid, int nbrows) {
    uint32_t aS = sb + s * A_STAGE;
    uint32_t bS = sb + SMEM_B_OFF + s * B_STAGE;
    #pragma unroll
    for (int j = 0; j < 5; ++j) {          // 320 rows * 4 granules / 256 thr
        int seg = tid + 256 * j;
        int r = seg >> 2, c = seg & 3;
        if (r < 128) {
            cpa16(aS + SWZ64(r, c), Ag + (size_t)r * K_DIM + k0 + c * 16);
        } else {
            int br = r - 128;
            if (br < nbrows)
                cpa16(bS + SWZ64(br, c), Bg + (size_t)br * K_DIM + k0 + c * 16);
        }
    }
}

__global__ void __launch_bounds__(256, 1)
hq_gemm(float* __restrict__ out, float k1) {
    extern __shared__ char smem[];
    const uint32_t sb = smem_u32(smem);
    const int tid = threadIdx.x;
    const int wid = tid >> 5, lane = tid & 31;
    const int warpM = wid & 3, warpN = wid >> 2;

    const int m0 = blockIdx.y * BM;
    const int n0 = blockIdx.x * BN;
    const bool full = (n0 + BN <= N_COLS);       // last tile: dp4a-only, 64 cols
    const int nbrows = full ? BN : (N_COLS - n0);
    const int dbase = full ? BNT : 0;            // dp4a smem B row base

    const int8_t* Ag = g_zx + (size_t)m0 * K_DIM;
    const int8_t* Bg = g_zw + (size_t)n0 * K_DIM;

    // ---- tensor-path ldmatrix address components (unchanged from R5) ----
    const int arow = warpM * 32 + (lane & 7) + ((lane >> 3) & 1) * 8;
    const int acadd = (lane >> 4) & 1;
    const int axor = (arow >> 1) & 3;
    const int brow = warpN * 64 + (lane & 7) + ((lane >> 4) & 1) * 8;
    const int bcadd = (lane >> 3) & 1;
    const int bxor = (brow >> 1) & 3;

    // ---- dp4a-path layout: warp = 32r x 32c, lane = 4r x 8c ----
    const int rpos = lane >> 2;                  // 0..7
    const int cpos = lane & 3;                   // 0..3
    const int dr0 = warpM * 32 + rpos * 4;       // first of 4 A rows
    const int dc0 = dbase + warpN * 32 + cpos * 8;  // first of 8 B smem rows
    uint32_t aoffs[4], boffs[8];                 // (row<<6) components + xor keys
    int akey[4], bkey[8];
    #pragma unroll
    for (int i = 0; i < 4; ++i) { aoffs[i] = (uint32_t)(dr0 + i) << 6; akey[i] = ((dr0 + i) >> 1) & 3; }
    #pragma unroll
    for (int j = 0; j < 8; ++j) { boffs[j] = (uint32_t)(dc0 + j) << 6; bkey[j] = ((dc0 + j) >> 1) & 3; }

    int acc[64];
    #pragma unroll
    for (int i = 0; i < 64; ++i) acc[i] = 0;
    int acc2[32];
    #pragma unroll
    for (int i = 0; i < 32; ++i) acc2[i] = 0;

    #pragma unroll
    for (int i = 0; i < NSTAGE - 1; ++i) {
        load_chunk(sb, Ag, Bg, i * BK, i, tid, nbrows);
        asm volatile("cp.async.commit_group;" ::: "memory");
    }

    for (int c = 0; c < NITER; ++c) {
        asm volatile("cp.async.wait_group 2;" ::: "memory");
        __syncthreads();

        if (c + NSTAGE - 1 < NITER)
            load_chunk(sb, Ag, Bg, (c + NSTAGE - 1) * BK,
                       (c + NSTAGE - 1) & (NSTAGE - 1), tid, nbrows);
        asm volatile("cp.async.commit_group;" ::: "memory");

        uint32_t aS = sb + (c & (NSTAGE - 1)) * A_STAGE;
        uint32_t bS = sb + SMEM_B_OFF + (c & (NSTAGE - 1)) * B_STAGE;

        #pragma unroll
        for (int kk = 0; kk < 2; ++kk) {
            // ---- tensor half-chunk (32 K) ----
            if (full) {
                uint32_t af[8], bf[16];
                #pragma unroll
                for (int ma = 0; ma < 2; ++ma)
                    ldm4(aS + (uint32_t)(arow + ma * 16) * 64 +
                             (uint32_t)(((2 * kk + acadd) ^ axor) << 4),
                         af[4*ma], af[4*ma+1], af[4*ma+2], af[4*ma+3]);
                #pragma unroll
                for (int nb = 0; nb < 4; ++nb)
                    ldm4(bS + (uint32_t)(brow + nb * 16) * 64 +
                             (uint32_t)(((2 * kk + bcadd) ^ bxor) << 4),
                         bf[4*nb], bf[4*nb+1], bf[4*nb+2], bf[4*nb+3]);
                #pragma unroll
                for (int ma = 0; ma < 2; ++ma)
                    #pragma unroll
                    for (int na = 0; na < 8; ++na)
                        mma_s8(acc + (ma * 8 + na) * 4, af + 4 * ma,
                               bf[(na >> 1) * 4 + (na & 1) * 2],
                               bf[(na >> 1) * 4 + (na & 1) * 2 + 1]);
            }
            // ---- dp4a: 2 x 16B k-blocks (32 K) on the fma pipe ----
            #pragma unroll
            for (int kb2 = 0; kb2 < 2; ++kb2) {
                int kb = kk * 2 + kb2;
                uint4 aw[4];
                #pragma unroll
                for (int i = 0; i < 4; ++i)
                    aw[i] = lds128(aS + aoffs[i] + (uint32_t)((kb ^ akey[i]) << 4));
                #pragma unroll
                for (int j = 0; j < 8; ++j) {
                    uint4 bw = lds128(bS + boffs[j] + (uint32_t)((kb ^ bkey[j]) << 4));
                    #pragma unroll
                    for (int i = 0; i < 4; ++i) {
                        int a0 = acc2[i * 8 + j];
                        a0 = dp4a_s(aw[i].x, bw.x, a0);
                        a0 = dp4a_s(aw[i].y, bw.y, a0);
                        a0 = dp4a_s(aw[i].z, bw.z, a0);
                        acc2[i * 8 + j] = dp4a_s(aw[i].w, bw.w, a0);
                    }
                }
            }
        }
    }

    // ---- epilogue: out = k1*acc + alpha[row] + beta[col] ----
    if (full) {
        #pragma unroll
        for (int ma = 0; ma < 2; ++ma) {
            int r0 = m0 + warpM * 32 + ma * 16 + (lane >> 2);
            float al0 = g_alpha[r0], al1 = g_alpha[r0 + 8];
            float* o0 = out + (size_t)r0 * N_COLS;
            float* o1 = out + (size_t)(r0 + 8) * N_COLS;
            #pragma unroll
            for (int na = 0; na < 8; ++na) {
                int col = n0 + warpN * 64 + na * 8 + (lane & 3) * 2;
                float b0 = g_beta[col], b1 = g_beta[col + 1];
                const int* d = acc + (ma * 8 + na) * 4;
                float2 p0, p1;
                p0.x = fmaf(k1, (float)d[0], al0 + b0);
                p0.y = fmaf(k1, (float)d[1], al0 + b1);
                p1.x = fmaf(k1, (float)d[2], al1 + b0);
                p1.y = fmaf(k1, (float)d[3], al1 + b1);
                *(float2*)(o0 + col) = p0;
                *(float2*)(o1 + col) = p1;
            }
        }
    }
    // dp4a region epilogue (always)
    {
        int cg = n0 + dc0;                       // global col of this lane's 8-col strip
        #pragma unroll
        for (int i = 0; i < 4; ++i) {
            int row = m0 + dr0 + i;
            float al = g_alpha[row];
            float* orow = out + (size_t)row * N_COLS + cg;
            const float* bp = g_beta + cg;
            float4 q0, q1;
            q0.x = fmaf(k1, (float)acc2[i*8+0], al + bp[0]);
            q0.y = fmaf(k1, (float)acc2[i*8+1], al + bp[1]);
            q0.z = fmaf(k1, (float)acc2[i*8+2], al + bp[2]);
            q0.w = fmaf(k1, (float)acc2[i*8+3], al + bp[3]);
            q1.x = fmaf(k1, (float)acc2[i*8+4], al + bp[4]);
            q1.y = fmaf(k1, (float)acc2[i*8+5], al + bp[5]);
            q1.z = fmaf(k1, (float)acc2[i*8+6], al + bp[6]);
            q1.w = fmaf(k1, (float)acc2[i*8+7], al + bp[7]);
            *(float4*)(orow) = q0;
            *(float4*)(orow + 4) = q1;
        }
    }
}

// ============================================================================
extern "C" void kernel_launch(void* const* d_in, const int* in_sizes, int n_in,
                              void* d_out, int out_size) {
    const float* x = (const float*)d_in[0];
    const float* w = (const float*)d_in[1];
    const float* bias = (const float*)d_in[2];
    float* out = (float*)d_out;

    const float scale = 768.0f / 255.0f;
    const float cc = -384.0f + 128.0f * scale;        // = 384/255
    const float k1 = scale * scale / (float)PADDED;
    const float kA = scale * cc / (float)PADDED;
    const float c2 = cc * cc;

    hq_fwht_quant<<<M_ROWS + N_COLS, 256>>>(x, w, bias, kA, c2);

    static_assert(SMEM_TOTAL == 81920, "smem");
    cudaFuncSetAttribute(hq_gemm, cudaFuncAttributeMaxDynamicSharedMemorySize, SMEM_TOTAL);
    dim3 grid((N_COLS + BN - 1) / BN, M_ROWS / BM);   // 22 x 64
    hq_gemm<<<grid, 256, SMEM_TOTAL>>>(out, k1);
}

// round 7
// speedup vs baseline: 1.5710x; 1.5710x over previous
#include <cuda_runtime.h>
#include <cstdint>

#define IN_FEAT 3072
#define PADDED  4096
#define M_ROWS  8192
#define N_COLS  4096
#define K_DIM   4096

#define BM 128
#define BNT 128              // tensor columns (warps 0-7)
#define BND 64               // dp4a columns (warps 8-15)
#define BN (BNT + BND)       // 192
#define BK 64
#define NSTAGE 4
#define NITER (K_DIM / BK)
#define NTHREADS 512

#define A_STAGE 8192                        // 128 rows x 64 B
#define B_STAGE (BN * BK)                   // 192 rows x 64 B = 12288
#define SMEM_B_OFF (NSTAGE * A_STAGE)       // 32768
#define SMEM_TOTAL (NSTAGE * (A_STAGE + B_STAGE))   // 81920

// -------- device scratch (static globals: no allocations allowed) ----------
__device__ int8_t g_zx[(size_t)M_ROWS * K_DIM];   // 32 MB
__device__ int8_t g_zw[(size_t)N_COLS * K_DIM];   // 16 MB
__device__ float  g_alpha[M_ROWS];
__device__ float  g_beta[N_COLS];

// -------- helpers -----------------------------------------------------------
__device__ __forceinline__ uint32_t smem_u32(const void* p) {
    uint32_t a;
    asm("{ .reg .u64 t; cvta.to.shared.u64 t, %1; cvt.u32.u64 %0, t; }"
        : "=r"(a) : "l"(p));
    return a;
}

__device__ __forceinline__ void cpa16(uint32_t sdst, const void* gsrc) {
    asm volatile("cp.async.cg.shared.global [%0], [%1], 16;" :: "r"(sdst), "l"(gsrc));
}

__device__ __forceinline__ void ldm4(uint32_t addr, uint32_t& r0, uint32_t& r1,
                                     uint32_t& r2, uint32_t& r3) {
    asm volatile("ldmatrix.sync.aligned.m8n8.x4.shared.b16 {%0,%1,%2,%3}, [%4];"
                 : "=r"(r0), "=r"(r1), "=r"(r2), "=r"(r3) : "r"(addr));
}

__device__ __forceinline__ void mma_s8(int* d, const uint32_t* a, uint32_t b0, uint32_t b1) {
    asm volatile(
        "mma.sync.aligned.m16n8k32.row.col.s32.s8.s8.s32 "
        "{%0,%1,%2,%3}, {%4,%5,%6,%7}, {%8,%9}, {%0,%1,%2,%3};"
        : "+r"(d[0]), "+r"(d[1]), "+r"(d[2]), "+r"(d[3])
        : "r"(a[0]), "r"(a[1]), "r"(a[2]), "r"(a[3]), "r"(b0), "r"(b1));
}

__device__ __forceinline__ uint4 lds128(uint32_t addr) {
    uint4 v;
    asm volatile("ld.shared.v4.u32 {%0,%1,%2,%3}, [%4];"
                 : "=r"(v.x), "=r"(v.y), "=r"(v.z), "=r"(v.w) : "r"(addr));
    return v;
}

__device__ __forceinline__ int dp4a_s(uint32_t a, uint32_t b, int c) {
    int d;
    asm("dp4a.s32.s32 %0, %1, %2, %3;" : "=r"(d) : "r"(a), "r"(b), "r"(c));
    return d;
}

// swizzle for 64-byte rows at 16B granules (cp.async / ldmatrix / LDS.128 safe)
#define SWZ64(row, c) (((uint32_t)(row) << 6) + ((((c) ^ (((row) >> 1) & 3)) & 3) << 4))

// ============================================================================
// Kernel 1: per-row pad -> FWHT(4096) -> quantize (z = q-128, int8) -> row sum
// ============================================================================
__global__ void __launch_bounds__(256)
hq_fwht_quant(const float* __restrict__ x, const float* __restrict__ w,
              const float* __restrict__ bias, float kA, float c2) {
    __shared__ float xch[PADDED];
    __shared__ float wsum[8];

    int row = blockIdx.x;
    int mode = (row >= M_ROWS);
    if (mode) row -= M_ROWS;
    const float* in = mode ? (w + (size_t)row * IN_FEAT) : (x + (size_t)row * IN_FEAT);
    const int t = threadIdx.x;

    float v[16];
    if (t < IN_FEAT / 16) {
        const float4* p = (const float4*)(in + t * 16);
        float4 a0 = p[0], a1 = p[1], a2 = p[2], a3 = p[3];
        v[0]=a0.x; v[1]=a0.y; v[2]=a0.z; v[3]=a0.w;
        v[4]=a1.x; v[5]=a1.y; v[6]=a1.z; v[7]=a1.w;
        v[8]=a2.x; v[9]=a2.y; v[10]=a2.z; v[11]=a2.w;
        v[12]=a3.x; v[13]=a3.y; v[14]=a3.z; v[15]=a3.w;
    } else {
        #pragma unroll
        for (int e = 0; e < 16; ++e) v[e] = 0.0f;
    }

    #pragma unroll
    for (int st = 1; st < 16; st <<= 1) {
        #pragma unroll
        for (int e = 0; e < 16; ++e)
            if (!(e & st)) {
                float a = v[e], b = v[e | st];
                v[e] = a + b;
                v[e | st] = a - b;
            }
    }
    #pragma unroll
    for (int b = 1; b <= 16; b <<= 1) {
        bool up = (t & b) != 0;
        #pragma unroll
        for (int e = 0; e < 16; ++e) {
            float o = __shfl_xor_sync(0xffffffffu, v[e], b, 32);
            v[e] = up ? (o - v[e]) : (v[e] + o);
        }
    }
    #pragma unroll
    for (int b = 32; b <= 128; b <<= 1) {
        __syncthreads();
        #pragma unroll
        for (int e = 0; e < 16; ++e) xch[e * 256 + t] = v[e];
        __syncthreads();
        int pt = t ^ b;
        bool up = (t & b) != 0;
        #pragma unroll
        for (int e = 0; e < 16; ++e) {
            float o = xch[e * 256 + pt];
            v[e] = up ? (o - v[e]) : (v[e] + o);
        }
    }

    const float inv_qs = 255.0f / 768.0f;
    int zi[16];
    float zsum = 0.0f;
    #pragma unroll
    for (int e = 0; e < 16; ++e) {
        float u = fminf(fmaxf(v[e], -384.0f), 384.0f);
        float q = fminf(fmaxf(rintf((u + 384.0f) * inv_qs), 0.0f), 255.0f);
        zi[e] = (int)q - 128;
        zsum += (float)zi[e];
    }
    uint32_t pk[4];
    #pragma unroll
    for (int j = 0; j < 4; ++j)
        pk[j] = (uint32_t)(zi[4*j] & 0xff) | ((uint32_t)(zi[4*j+1] & 0xff) << 8) |
                ((uint32_t)(zi[4*j+2] & 0xff) << 16) | ((uint32_t)(zi[4*j+3] & 0xff) << 24);
    int8_t* oz = (mode ? g_zw : g_zx) + (size_t)row * PADDED + t * 16;
    *(uint4*)oz = make_uint4(pk[0], pk[1], pk[2], pk[3]);

    #pragma unroll
    for (int off = 16; off > 0; off >>= 1)
        zsum += __shfl_down_sync(0xffffffffu, zsum, off, 32);
    if ((t & 31) == 0) wsum[t >> 5] = zsum;
    __syncthreads();
    if (t == 0) {
        float S = 0.0f;
        #pragma unroll
        for (int i = 0; i < 8; ++i) S += wsum[i];
        float stat = kA * S;
        if (mode) g_beta[row] = stat + c2 + bias[row];
        else      g_alpha[row] = stat;
    }
}

// ============================================================================
// Kernel 2: warp-specialized hybrid GEMM, tile 128 x 192.
//   warps 0-7  : mma.sync path (tensor pipe), cols 0..127  -- identical to R5
//   warps 8-15 : dp4a path (fma pipe),        cols 128..191
// One shared A tile, 4-stage cp.async, 512 threads, 1 CTA/SM.
// ============================================================================
__device__ __forceinline__ void load_chunk(uint32_t sb, const int8_t* Ag, const int8_t* Bg,
                                           int k0, int s, int tid, int nbrows) {
    uint32_t aS = sb + s * A_STAGE;
    uint32_t bS = sb + SMEM_B_OFF + s * B_STAGE;
    #pragma unroll
    for (int j = 0; j < 3; ++j) {          // (128+192) rows * 4 granules = 1280
        int seg = tid + NTHREADS * j;
        if (seg >= 1280) break;
        int r = seg >> 2, c = seg & 3;
        if (r < 128) {
            cpa16(aS + SWZ64(r, c), Ag + (size_t)r * K_DIM + k0 + c * 16);
        } else {
            int br = r - 128;
            if (br < nbrows)
                cpa16(bS + SWZ64(br, c), Bg + (size_t)br * K_DIM + k0 + c * 16);
        }
    }
}

__global__ void __launch_bounds__(NTHREADS, 1)
hq_gemm(float* __restrict__ out, float k1) {
    extern __shared__ char smem[];
    const uint32_t sb = smem_u32(smem);
    const int tid = threadIdx.x;
    const int wid = tid >> 5, lane = tid & 31;

    const int m0 = blockIdx.y * BM;
    const int n0 = blockIdx.x * BN;
    const bool full = (n0 + BN <= N_COLS);       // last tile: 64 cols, tensor-only
    const int nbrows = full ? BN : (N_COLS - n0);

    const int8_t* Ag = g_zx + (size_t)m0 * K_DIM;
    const int8_t* Bg = g_zw + (size_t)n0 * K_DIM;

    #pragma unroll
    for (int i = 0; i < NSTAGE - 1; ++i) {
        load_chunk(sb, Ag, Bg, i * BK, i, tid, nbrows);
        asm volatile("cp.async.commit_group;" ::: "memory");
    }

    if (wid < 8) {
        // ==================== tensor warps (R5 path) ====================
        const int warpM = wid & 3, warpN = wid >> 2;
        const bool active = full || (warpN == 0);

        const int arow = warpM * 32 + (lane & 7) + ((lane >> 3) & 1) * 8;
        const int acadd = (lane >> 4) & 1;
        const int axor = (arow >> 1) & 3;
        const int brow = warpN * 64 + (lane & 7) + ((lane >> 4) & 1) * 8;
        const int bcadd = (lane >> 3) & 1;
        const int bxor = (brow >> 1) & 3;

        int acc[64];
        #pragma unroll
        for (int i = 0; i < 64; ++i) acc[i] = 0;

        for (int c = 0; c < NITER; ++c) {
            asm volatile("cp.async.wait_group 2;" ::: "memory");
            __syncthreads();
            if (c + NSTAGE - 1 < NITER)
                load_chunk(sb, Ag, Bg, (c + NSTAGE - 1) * BK,
                           (c + NSTAGE - 1) & (NSTAGE - 1), tid, nbrows);
            asm volatile("cp.async.commit_group;" ::: "memory");

            if (active) {
                uint32_t aS = sb + (c & (NSTAGE - 1)) * A_STAGE;
                uint32_t bS = sb + SMEM_B_OFF + (c & (NSTAGE - 1)) * B_STAGE;
                #pragma unroll
                for (int kk = 0; kk < 2; ++kk) {
                    uint32_t af[8], bf[16];
                    #pragma unroll
                    for (int ma = 0; ma < 2; ++ma)
                        ldm4(aS + (uint32_t)(arow + ma * 16) * 64 +
                                 (uint32_t)(((2 * kk + acadd) ^ axor) << 4),
                             af[4*ma], af[4*ma+1], af[4*ma+2], af[4*ma+3]);
                    #pragma unroll
                    for (int nb = 0; nb < 4; ++nb)
                        ldm4(bS + (uint32_t)(brow + nb * 16) * 64 +
                                 (uint32_t)(((2 * kk + bcadd) ^ bxor) << 4),
                             bf[4*nb], bf[4*nb+1], bf[4*nb+2], bf[4*nb+3]);
                    #pragma unroll
                    for (int ma = 0; ma < 2; ++ma)
                        #pragma unroll
                        for (int na = 0; na < 8; ++na)
                            mma_s8(acc + (ma * 8 + na) * 4, af + 4 * ma,
                                   bf[(na >> 1) * 4 + (na & 1) * 2],
                                   bf[(na >> 1) * 4 + (na & 1) * 2 + 1]);
                }
            }
        }

        if (active) {
            #pragma unroll
            for (int ma = 0; ma < 2; ++ma) {
                int r0 = m0 + warpM * 32 + ma * 16 + (lane >> 2);
                float al0 = g_alpha[r0], al1 = g_alpha[r0 + 8];
                float* o0 = out + (size_t)r0 * N_COLS;
                float* o1 = out + (size_t)(r0 + 8) * N_COLS;
                #pragma unroll
                for (int na = 0; na < 8; ++na) {
                    int col = n0 + warpN * 64 + na * 8 + (lane & 3) * 2;
                    float b0 = g_beta[col], b1 = g_beta[col + 1];
                    const int* d = acc + (ma * 8 + na) * 4;
                    float2 p0, p1;
                    p0.x = fmaf(k1, (float)d[0], al0 + b0);
                    p0.y = fmaf(k1, (float)d[1], al0 + b1);
                    p1.x = fmaf(k1, (float)d[2], al1 + b0);
                    p1.y = fmaf(k1, (float)d[3], al1 + b1);
                    *(float2*)(o0 + col) = p0;
                    *(float2*)(o1 + col) = p1;
                }
            }
        }
    } else {
        // ==================== dp4a warps ====================
        const int dwid = wid - 8;
        const int warpMd = dwid & 3;            // 4 groups x 32 rows
        const int warpNd = dwid >> 2;           // 2 groups x 32 cols
        const int dr0 = warpMd * 32 + (lane >> 2) * 4;          // 4 A rows
        const int db0 = BNT + warpNd * 32 + (lane & 3) * 8;     // 8 B smem rows

        uint32_t aoffs[4], boffs[8];
        int akey[4], bkey[8];
        #pragma unroll
        for (int i = 0; i < 4; ++i) {
            aoffs[i] = (uint32_t)(dr0 + i) << 6;
            akey[i] = ((dr0 + i) >> 1) & 3;
        }
        #pragma unroll
        for (int j = 0; j < 8; ++j) {
            boffs[j] = (uint32_t)(db0 + j) << 6;
            bkey[j] = ((db0 + j) >> 1) & 3;
        }

        int acc2[32];
        #pragma unroll
        for (int i = 0; i < 32; ++i) acc2[i] = 0;

        for (int c = 0; c < NITER; ++c) {
            asm volatile("cp.async.wait_group 2;" ::: "memory");
            __syncthreads();
            if (c + NSTAGE - 1 < NITER)
                load_chunk(sb, Ag, Bg, (c + NSTAGE - 1) * BK,
                           (c + NSTAGE - 1) & (NSTAGE - 1), tid, nbrows);
            asm volatile("cp.async.commit_group;" ::: "memory");

            if (full) {
                uint32_t aS = sb + (c & (NSTAGE - 1)) * A_STAGE;
                uint32_t bS = sb + SMEM_B_OFF + (c & (NSTAGE - 1)) * B_STAGE;
                #pragma unroll
                for (int kb = 0; kb < 4; ++kb) {
                    uint4 aw[4];
                    #pragma unroll
                    for (int i = 0; i < 4; ++i)
                        aw[i] = lds128(aS + aoffs[i] + (uint32_t)((kb ^ akey[i]) << 4));
                    #pragma unroll
                    for (int j = 0; j < 8; ++j) {
                        uint4 bw = lds128(bS + boffs[j] + (uint32_t)((kb ^ bkey[j]) << 4));
                        #pragma unroll
                        for (int i = 0; i < 4; ++i) {
                            int a0 = acc2[i * 8 + j];
                            a0 = dp4a_s(aw[i].x, bw.x, a0);
                            a0 = dp4a_s(aw[i].y, bw.y, a0);
                            a0 = dp4a_s(aw[i].z, bw.z, a0);
                            acc2[i * 8 + j] = dp4a_s(aw[i].w, bw.w, a0);
                        }
                    }
                }
            }
        }

        if (full) {
            int cg = n0 + db0;                  // global first col of 8-col strip
            #pragma unroll
            for (int i = 0; i < 4; ++i) {
                int row = m0 + dr0 + i;
                float al = g_alpha[row];
                float* orow = out + (size_t)row * N_COLS + cg;
                const float* bp = g_beta + cg;
                float4 q0, q1;
                q0.x = fmaf(k1, (float)acc2[i*8+0], al + bp[0]);
                q0.y = fmaf(k1, (float)acc2[i*8+1], al + bp[1]);
                q0.z = fmaf(k1, (float)acc2[i*8+2], al + bp[2]);
                q0.w = fmaf(k1, (float)acc2[i*8+3], al + bp[3]);
                q1.x = fmaf(k1, (float)acc2[i*8+4], al + bp[4]);
                q1.y = fmaf(k1, (float)acc2[i*8+5], al + bp[5]);
                q1.z = fmaf(k1, (float)acc2[i*8+6], al + bp[6]);
                q1.w = fmaf(k1, (float)acc2[i*8+7], al + bp[7]);
                *(float4*)(orow) = q0;
                *(float4*)(orow + 4) = q1;
            }
        }
    }
}

// ============================================================================
extern "C" void kernel_launch(void* const* d_in, const int* in_sizes, int n_in,
                              void* d_out, int out_size) {
    const float* x = (const float*)d_in[0];
    const float* w = (const float*)d_in[1];
    const float* bias = (const float*)d_in[2];
    float* out = (float*)d_out;

    const float scale = 768.0f / 255.0f;
    const float cc = -384.0f + 128.0f * scale;        // = 384/255
    const float k1 = scale * scale / (float)PADDED;
    const float kA = scale * cc / (float)PADDED;
    const float c2 = cc * cc;

    hq_fwht_quant<<<M_ROWS + N_COLS, 256>>>(x, w, bias, kA, c2);

    static_assert(SMEM_TOTAL == 81920, "smem");
    cudaFuncSetAttribute(hq_gemm, cudaFuncAttributeMaxDynamicSharedMemorySize, SMEM_TOTAL);
    dim3 grid((N_COLS + BN - 1) / BN, M_ROWS / BM);   // 22 x 64
    hq_gemm<<<grid, NTHREADS, SMEM_TOTAL>>>(out, k1);
}

// round 8
// speedup vs baseline: 1.7348x; 1.1042x over previous
#include <cuda_runtime.h>
#include <cstdint>

#define IN_FEAT 3072
#define PADDED  4096
#define M_ROWS  8192
#define N_COLS  4096
#define K_DIM   4096

#define BM 128
#define BNT 128              // tensor columns (warps 0-7)
#define BND 64               // dp4a columns (warps 8-15)
#define BN (BNT + BND)       // 192
#define BK 64
#define NSTAGE 4
#define NITER (K_DIM / BK)
#define NTHREADS 512

#define A_STAGE 8192                        // 128 rows x 64 B
#define B_STAGE (BN * BK)                   // 192 rows x 64 B = 12288
#define SMEM_B_OFF (NSTAGE * A_STAGE)       // 32768
#define SMEM_TOTAL (NSTAGE * (A_STAGE + B_STAGE))   // 81920

// -------- device scratch (static globals: no allocations allowed) ----------
__device__ int8_t g_zx[(size_t)M_ROWS * K_DIM];   // 32 MB
__device__ int8_t g_zw[(size_t)N_COLS * K_DIM];   // 16 MB
__device__ float  g_alpha[M_ROWS];
__device__ float  g_beta[N_COLS];

// -------- helpers -----------------------------------------------------------
__device__ __forceinline__ uint32_t smem_u32(const void* p) {
    uint32_t a;
    asm("{ .reg .u64 t; cvta.to.shared.u64 t, %1; cvt.u32.u64 %0, t; }"
        : "=r"(a) : "l"(p));
    return a;
}

__device__ __forceinline__ void cpa16(uint32_t sdst, const void* gsrc) {
    asm volatile("cp.async.cg.shared.global [%0], [%1], 16;" :: "r"(sdst), "l"(gsrc));
}

__device__ __forceinline__ void ldm4(uint32_t addr, uint32_t& r0, uint32_t& r1,
                                     uint32_t& r2, uint32_t& r3) {
    asm volatile("ldmatrix.sync.aligned.m8n8.x4.shared.b16 {%0,%1,%2,%3}, [%4];"
                 : "=r"(r0), "=r"(r1), "=r"(r2), "=r"(r3) : "r"(addr));
}

__device__ __forceinline__ void mma_s8(int* d, const uint32_t* a, uint32_t b0, uint32_t b1) {
    asm volatile(
        "mma.sync.aligned.m16n8k32.row.col.s32.s8.s8.s32 "
        "{%0,%1,%2,%3}, {%4,%5,%6,%7}, {%8,%9}, {%0,%1,%2,%3};"
        : "+r"(d[0]), "+r"(d[1]), "+r"(d[2]), "+r"(d[3])
        : "r"(a[0]), "r"(a[1]), "r"(a[2]), "r"(a[3]), "r"(b0), "r"(b1));
}

__device__ __forceinline__ uint4 lds128(uint32_t addr) {
    uint4 v;
    asm volatile("ld.shared.v4.u32 {%0,%1,%2,%3}, [%4];"
                 : "=r"(v.x), "=r"(v.y), "=r"(v.z), "=r"(v.w) : "r"(addr));
    return v;
}

__device__ __forceinline__ int dp4a_s(uint32_t a, uint32_t b, int c) {
    int d;
    asm("dp4a.s32.s32 %0, %1, %2, %3;" : "=r"(d) : "r"(a), "r"(b), "r"(c));
    return d;
}

// swizzle for 64-byte rows at 16B granules (cp.async / ldmatrix / LDS.128 safe)
#define SWZ64(row, c) (((uint32_t)(row) << 6) + ((((c) ^ (((row) >> 1) & 3)) & 3) << 4))

// ============================================================================
// Kernel 1: per-row pad -> FWHT(4096) -> quantize (z = q-128, int8) -> row sum
// ============================================================================
__global__ void __launch_bounds__(256)
hq_fwht_quant(const float* __restrict__ x, const float* __restrict__ w,
              const float* __restrict__ bias, float kA, float c2) {
    __shared__ float xch[PADDED];
    __shared__ float wsum[8];

    int row = blockIdx.x;
    int mode = (row >= M_ROWS);
    if (mode) row -= M_ROWS;
    const float* in = mode ? (w + (size_t)row * IN_FEAT) : (x + (size_t)row * IN_FEAT);
    const int t = threadIdx.x;

    float v[16];
    if (t < IN_FEAT / 16) {
        const float4* p = (const float4*)(in + t * 16);
        float4 a0 = p[0], a1 = p[1], a2 = p[2], a3 = p[3];
        v[0]=a0.x; v[1]=a0.y; v[2]=a0.z; v[3]=a0.w;
        v[4]=a1.x; v[5]=a1.y; v[6]=a1.z; v[7]=a1.w;
        v[8]=a2.x; v[9]=a2.y; v[10]=a2.z; v[11]=a2.w;
        v[12]=a3.x; v[13]=a3.y; v[14]=a3.z; v[15]=a3.w;
    } else {
        #pragma unroll
        for (int e = 0; e < 16; ++e) v[e] = 0.0f;
    }

    #pragma unroll
    for (int st = 1; st < 16; st <<= 1) {
        #pragma unroll
        for (int e = 0; e < 16; ++e)
            if (!(e & st)) {
                float a = v[e], b = v[e | st];
                v[e] = a + b;
                v[e | st] = a - b;
            }
    }
    #pragma unroll
    for (int b = 1; b <= 16; b <<= 1) {
        bool up = (t & b) != 0;
        #pragma unroll
        for (int e = 0; e < 16; ++e) {
            float o = __shfl_xor_sync(0xffffffffu, v[e], b, 32);
            v[e] = up ? (o - v[e]) : (v[e] + o);
        }
    }
    #pragma unroll
    for (int b = 32; b <= 128; b <<= 1) {
        __syncthreads();
        #pragma unroll
        for (int e = 0; e < 16; ++e) xch[e * 256 + t] = v[e];
        __syncthreads();
        int pt = t ^ b;
        bool up = (t & b) != 0;
        #pragma unroll
        for (int e = 0; e < 16; ++e) {
            float o = xch[e * 256 + pt];
            v[e] = up ? (o - v[e]) : (v[e] + o);
        }
    }

    const float inv_qs = 255.0f / 768.0f;
    int zi[16];
    float zsum = 0.0f;
    #pragma unroll
    for (int e = 0; e < 16; ++e) {
        float u = fminf(fmaxf(v[e], -384.0f), 384.0f);
        float q = fminf(fmaxf(rintf((u + 384.0f) * inv_qs), 0.0f), 255.0f);
        zi[e] = (int)q - 128;
        zsum += (float)zi[e];
    }
    uint32_t pk[4];
    #pragma unroll
    for (int j = 0; j < 4; ++j)
        pk[j] = (uint32_t)(zi[4*j] & 0xff) | ((uint32_t)(zi[4*j+1] & 0xff) << 8) |
                ((uint32_t)(zi[4*j+2] & 0xff) << 16) | ((uint32_t)(zi[4*j+3] & 0xff) << 24);
    int8_t* oz = (mode ? g_zw : g_zx) + (size_t)row * PADDED + t * 16;
    *(uint4*)oz = make_uint4(pk[0], pk[1], pk[2], pk[3]);

    #pragma unroll
    for (int off = 16; off > 0; off >>= 1)
        zsum += __shfl_down_sync(0xffffffffu, zsum, off, 32);
    if ((t & 31) == 0) wsum[t >> 5] = zsum;
    __syncthreads();
    if (t == 0) {
        float S = 0.0f;
        #pragma unroll
        for (int i = 0; i < 8; ++i) S += wsum[i];
        float stat = kA * S;
        if (mode) g_beta[row] = stat + c2 + bias[row];
        else      g_alpha[row] = stat;
    }
}

// ============================================================================
// Kernel 2: warp-specialized hybrid GEMM, tile 128 x 192.
//   warps 0-7  : mma.sync path (tensor pipe), cols 0..127
//   warps 8-15 : dp4a path (fma pipe), cols 128..191 -- rows/cols assigned
//                INTERLEAVED (stride 8 / stride 4) so LDS.128 is conflict-free
// ============================================================================
__device__ __forceinline__ void load_chunk(uint32_t sb, const int8_t* Ag, const int8_t* Bg,
                                           int k0, int s, int tid, int nbrows) {
    uint32_t aS = sb + s * A_STAGE;
    uint32_t bS = sb + SMEM_B_OFF + s * B_STAGE;
    #pragma unroll
    for (int j = 0; j < 3; ++j) {          // (128+192) rows * 4 granules = 1280
        int seg = tid + NTHREADS * j;
        if (seg >= 1280) break;
        int r = seg >> 2, c = seg & 3;
        if (r < 128) {
            cpa16(aS + SWZ64(r, c), Ag + (size_t)r * K_DIM + k0 + c * 16);
        } else {
            int br = r - 128;
            if (br < nbrows)
                cpa16(bS + SWZ64(br, c), Bg + (size_t)br * K_DIM + k0 + c * 16);
        }
    }
}

__global__ void __launch_bounds__(NTHREADS, 1)
hq_gemm(float* __restrict__ out, float k1) {
    extern __shared__ char smem[];
    const uint32_t sb = smem_u32(smem);
    const int tid = threadIdx.x;
    const int wid = tid >> 5, lane = tid & 31;

    const int m0 = blockIdx.y * BM;
    const int n0 = blockIdx.x * BN;
    const bool full = (n0 + BN <= N_COLS);       // last tile: 64 cols, tensor-only
    const int nbrows = full ? BN : (N_COLS - n0);

    const int8_t* Ag = g_zx + (size_t)m0 * K_DIM;
    const int8_t* Bg = g_zw + (size_t)n0 * K_DIM;

    #pragma unroll
    for (int i = 0; i < NSTAGE - 1; ++i) {
        load_chunk(sb, Ag, Bg, i * BK, i, tid, nbrows);
        asm volatile("cp.async.commit_group;" ::: "memory");
    }

    if (wid < 8) {
        // ==================== tensor warps ====================
        const int warpM = wid & 3, warpN = wid >> 2;
        const bool active = full || (warpN == 0);

        const int arow = warpM * 32 + (lane & 7) + ((lane >> 3) & 1) * 8;
        const int acadd = (lane >> 4) & 1;
        const int axor = (arow >> 1) & 3;
        const int brow = warpN * 64 + (lane & 7) + ((lane >> 4) & 1) * 8;
        const int bcadd = (lane >> 3) & 1;
        const int bxor = (brow >> 1) & 3;

        int acc[64];
        #pragma unroll
        for (int i = 0; i < 64; ++i) acc[i] = 0;

        for (int c = 0; c < NITER; ++c) {
            asm volatile("cp.async.wait_group 2;" ::: "memory");
            __syncthreads();
            if (c + NSTAGE - 1 < NITER)
                load_chunk(sb, Ag, Bg, (c + NSTAGE - 1) * BK,
                           (c + NSTAGE - 1) & (NSTAGE - 1), tid, nbrows);
            asm volatile("cp.async.commit_group;" ::: "memory");

            if (active) {
                uint32_t aS = sb + (c & (NSTAGE - 1)) * A_STAGE;
                uint32_t bS = sb + SMEM_B_OFF + (c & (NSTAGE - 1)) * B_STAGE;
                #pragma unroll
                for (int kk = 0; kk < 2; ++kk) {
                    uint32_t af[8], bf[16];
                    #pragma unroll
                    for (int ma = 0; ma < 2; ++ma)
                        ldm4(aS + (uint32_t)(arow + ma * 16) * 64 +
                                 (uint32_t)(((2 * kk + acadd) ^ axor) << 4),
                             af[4*ma], af[4*ma+1], af[4*ma+2], af[4*ma+3]);
                    #pragma unroll
                    for (int nb = 0; nb < 4; ++nb)
                        ldm4(bS + (uint32_t)(brow + nb * 16) * 64 +
                                 (uint32_t)(((2 * kk + bcadd) ^ bxor) << 4),
                             bf[4*nb], bf[4*nb+1], bf[4*nb+2], bf[4*nb+3]);
                    #pragma unroll
                    for (int ma = 0; ma < 2; ++ma)
                        #pragma unroll
                        for (int na = 0; na < 8; ++na)
                            mma_s8(acc + (ma * 8 + na) * 4, af + 4 * ma,
                                   bf[(na >> 1) * 4 + (na & 1) * 2],
                                   bf[(na >> 1) * 4 + (na & 1) * 2 + 1]);
                }
            }
        }

        if (active) {
            #pragma unroll
            for (int ma = 0; ma < 2; ++ma) {
                int r0 = m0 + warpM * 32 + ma * 16 + (lane >> 2);
                float al0 = g_alpha[r0], al1 = g_alpha[r0 + 8];
                float* o0 = out + (size_t)r0 * N_COLS;
                float* o1 = out + (size_t)(r0 + 8) * N_COLS;
                #pragma unroll
                for (int na = 0; na < 8; ++na) {
                    int col = n0 + warpN * 64 + na * 8 + (lane & 3) * 2;
                    float b0 = g_beta[col], b1 = g_beta[col + 1];
                    const int* d = acc + (ma * 8 + na) * 4;
                    float2 p0, p1;
                    p0.x = fmaf(k1, (float)d[0], al0 + b0);
                    p0.y = fmaf(k1, (float)d[1], al0 + b1);
                    p1.x = fmaf(k1, (float)d[2], al1 + b0);
                    p1.y = fmaf(k1, (float)d[3], al1 + b1);
                    *(float2*)(o0 + col) = p0;
                    *(float2*)(o1 + col) = p1;
                }
            }
        }
    } else {
        // ==================== dp4a warps (interleaved, conflict-free) ======
        const int dwid = wid - 8;
        const int warpMd = dwid & 3;            // 4 groups x 32 rows
        const int warpNd = dwid >> 2;           // 2 groups x 32 cols
        // A rows: dr0 + 8*i  (i=0..3) -> per-instruction set = 8 consecutive rows
        const int dr0 = warpMd * 32 + (lane >> 2);
        // B smem rows (tile cols): db0 + 4*j (j=0..7) -> per-instr = 4 consecutive
        const int db0 = BNT + warpNd * 32 + (lane & 3);

        uint32_t aoffs[4], boffs[8];
        int akey[4], bkey[8];
        #pragma unroll
        for (int i = 0; i < 4; ++i) {
            int r = dr0 + 8 * i;
            aoffs[i] = (uint32_t)r << 6;
            akey[i] = (r >> 1) & 3;
        }
        #pragma unroll
        for (int j = 0; j < 8; ++j) {
            int r = db0 + 4 * j;
            boffs[j] = (uint32_t)r << 6;
            bkey[j] = (r >> 1) & 3;
        }

        int acc2[32];
        #pragma unroll
        for (int i = 0; i < 32; ++i) acc2[i] = 0;

        for (int c = 0; c < NITER; ++c) {
            asm volatile("cp.async.wait_group 2;" ::: "memory");
            __syncthreads();
            if (c + NSTAGE - 1 < NITER)
                load_chunk(sb, Ag, Bg, (c + NSTAGE - 1) * BK,
                           (c + NSTAGE - 1) & (NSTAGE - 1), tid, nbrows);
            asm volatile("cp.async.commit_group;" ::: "memory");

            if (full) {
                uint32_t aS = sb + (c & (NSTAGE - 1)) * A_STAGE;
                uint32_t bS = sb + SMEM_B_OFF + (c & (NSTAGE - 1)) * B_STAGE;
                #pragma unroll
                for (int kb = 0; kb < 4; ++kb) {
                    uint4 aw[4];
                    #pragma unroll
                    for (int i = 0; i < 4; ++i)
                        aw[i] = lds128(aS + aoffs[i] + (uint32_t)((kb ^ akey[i]) << 4));
                    #pragma unroll
                    for (int j = 0; j < 8; ++j) {
                        uint4 bw = lds128(bS + boffs[j] + (uint32_t)((kb ^ bkey[j]) << 4));
                        #pragma unroll
                        for (int i = 0; i < 4; ++i) {
                            int a0 = acc2[i * 8 + j];
                            a0 = dp4a_s(aw[i].x, bw.x, a0);
                            a0 = dp4a_s(aw[i].y, bw.y, a0);
                            a0 = dp4a_s(aw[i].z, bw.z, a0);
                            acc2[i * 8 + j] = dp4a_s(aw[i].w, bw.w, a0);
                        }
                    }
                }
            }
        }

        if (full) {
            #pragma unroll
            for (int i = 0; i < 4; ++i) {
                int row = m0 + dr0 + 8 * i;
                float al = g_alpha[row];
                float* orow = out + (size_t)row * N_COLS;
                #pragma unroll
                for (int j = 0; j < 8; ++j) {
                    int col = n0 + db0 + 4 * j;
                    orow[col] = fmaf(k1, (float)acc2[i * 8 + j], al + g_beta[col]);
                }
            }
        }
    }
}

// ============================================================================
extern "C" void kernel_launch(void* const* d_in, const int* in_sizes, int n_in,
                              void* d_out, int out_size) {
    const float* x = (const float*)d_in[0];
    const float* w = (const float*)d_in[1];
    const float* bias = (const float*)d_in[2];
    float* out = (float*)d_out;

    const float scale = 768.0f / 255.0f;
    const float cc = -384.0f + 128.0f * scale;        // = 384/255
    const float k1 = scale * scale / (float)PADDED;
    const float kA = scale * cc / (float)PADDED;
    const float c2 = cc * cc;

    hq_fwht_quant<<<M_ROWS + N_COLS, 256>>>(x, w, bias, kA, c2);

    static_assert(SMEM_TOTAL == 81920, "smem");
    cudaFuncSetAttribute(hq_gemm, cudaFuncAttributeMaxDynamicSharedMemorySize, SMEM_TOTAL);
    dim3 grid((N_COLS + BN - 1) / BN, M_ROWS / BM);   // 22 x 64
    hq_gemm<<<grid, NTHREADS, SMEM_TOTAL>>>(out, k1);
}

// round 9
// speedup vs baseline: 1.8784x; 1.0828x over previous
#include <cuda_runtime.h>
#include <cstdint>

#define IN_FEAT 3072
#define PADDED  4096
#define M_ROWS  8192
#define N_COLS  4096
#define K_DIM   4096

#define BM 128
#define BNT 128              // tensor columns (warps 0-7)
#define BND 64               // dp4a columns (warps 8-15)
#define BN (BNT + BND)       // 192
#define BK 64
#define NSTAGE 6             // 3 pair-slots x 2 chunks
#define NITER (K_DIM / BK)   // 64
#define NPAIR (NITER / 2)    // 32
#define NTHREADS 512

#define A_STAGE 8192                        // 128 rows x 64 B
#define B_STAGE (BN * BK)                   // 192 rows x 64 B = 12288
#define SMEM_B_OFF (NSTAGE * A_STAGE)       // 49152
#define SMEM_TOTAL (NSTAGE * (A_STAGE + B_STAGE))   // 122880

// -------- device scratch (static globals: no allocations allowed) ----------
__device__ int8_t g_zx[(size_t)M_ROWS * K_DIM];   // 32 MB
__device__ int8_t g_zw[(size_t)N_COLS * K_DIM];   // 16 MB
__device__ float  g_alpha[M_ROWS];
__device__ float  g_beta[N_COLS];

// -------- helpers -----------------------------------------------------------
__device__ __forceinline__ uint32_t smem_u32(const void* p) {
    uint32_t a;
    asm("{ .reg .u64 t; cvta.to.shared.u64 t, %1; cvt.u32.u64 %0, t; }"
        : "=r"(a) : "l"(p));
    return a;
}

__device__ __forceinline__ void cpa16(uint32_t sdst, const void* gsrc) {
    asm volatile("cp.async.cg.shared.global [%0], [%1], 16;" :: "r"(sdst), "l"(gsrc));
}

__device__ __forceinline__ void ldm4(uint32_t addr, uint32_t& r0, uint32_t& r1,
                                     uint32_t& r2, uint32_t& r3) {
    asm volatile("ldmatrix.sync.aligned.m8n8.x4.shared.b16 {%0,%1,%2,%3}, [%4];"
                 : "=r"(r0), "=r"(r1), "=r"(r2), "=r"(r3) : "r"(addr));
}

__device__ __forceinline__ void mma_s8(int* d, const uint32_t* a, uint32_t b0, uint32_t b1) {
    asm volatile(
        "mma.sync.aligned.m16n8k32.row.col.s32.s8.s8.s32 "
        "{%0,%1,%2,%3}, {%4,%5,%6,%7}, {%8,%9}, {%0,%1,%2,%3};"
        : "+r"(d[0]), "+r"(d[1]), "+r"(d[2]), "+r"(d[3])
        : "r"(a[0]), "r"(a[1]), "r"(a[2]), "r"(a[3]), "r"(b0), "r"(b1));
}

__device__ __forceinline__ uint4 lds128(uint32_t addr) {
    uint4 v;
    asm volatile("ld.shared.v4.u32 {%0,%1,%2,%3}, [%4];"
                 : "=r"(v.x), "=r"(v.y), "=r"(v.z), "=r"(v.w) : "r"(addr));
    return v;
}

__device__ __forceinline__ int dp4a_s(uint32_t a, uint32_t b, int c) {
    int d;
    asm("dp4a.s32.s32 %0, %1, %2, %3;" : "=r"(d) : "r"(a), "r"(b), "r"(c));
    return d;
}

// swizzle for 64-byte rows at 16B granules (cp.async / ldmatrix / LDS.128 safe)
#define SWZ64(row, c) (((uint32_t)(row) << 6) + ((((c) ^ (((row) >> 1) & 3)) & 3) << 4))

// ============================================================================
// Kernel 1: per-row pad -> FWHT(4096) -> quantize (z = q-128, int8) -> row sum
// ============================================================================
__global__ void __launch_bounds__(256)
hq_fwht_quant(const float* __restrict__ x, const float* __restrict__ w,
              const float* __restrict__ bias, float kA, float c2) {
    __shared__ float xch[PADDED];
    __shared__ float wsum[8];

    int row = blockIdx.x;
    int mode = (row >= M_ROWS);
    if (mode) row -= M_ROWS;
    const float* in = mode ? (w + (size_t)row * IN_FEAT) : (x + (size_t)row * IN_FEAT);
    const int t = threadIdx.x;

    float v[16];
    if (t < IN_FEAT / 16) {
        const float4* p = (const float4*)(in + t * 16);
        float4 a0 = p[0], a1 = p[1], a2 = p[2], a3 = p[3];
        v[0]=a0.x; v[1]=a0.y; v[2]=a0.z; v[3]=a0.w;
        v[4]=a1.x; v[5]=a1.y; v[6]=a1.z; v[7]=a1.w;
        v[8]=a2.x; v[9]=a2.y; v[10]=a2.z; v[11]=a2.w;
        v[12]=a3.x; v[13]=a3.y; v[14]=a3.z; v[15]=a3.w;
    } else {
        #pragma unroll
        for (int e = 0; e < 16; ++e) v[e] = 0.0f;
    }

    #pragma unroll
    for (int st = 1; st < 16; st <<= 1) {
        #pragma unroll
        for (int e = 0; e < 16; ++e)
            if (!(e & st)) {
                float a = v[e], b = v[e | st];
                v[e] = a + b;
                v[e | st] = a - b;
            }
    }
    #pragma unroll
    for (int b = 1; b <= 16; b <<= 1) {
        bool up = (t & b) != 0;
        #pragma unroll
        for (int e = 0; e < 16; ++e) {
            float o = __shfl_xor_sync(0xffffffffu, v[e], b, 32);
            v[e] = up ? (o - v[e]) : (v[e] + o);
        }
    }
    #pragma unroll
    for (int b = 32; b <= 128; b <<= 1) {
        __syncthreads();
        #pragma unroll
        for (int e = 0; e < 16; ++e) xch[e * 256 + t] = v[e];
        __syncthreads();
        int pt = t ^ b;
        bool up = (t & b) != 0;
        #pragma unroll
        for (int e = 0; e < 16; ++e) {
            float o = xch[e * 256 + pt];
            v[e] = up ? (o - v[e]) : (v[e] + o);
        }
    }

    const float inv_qs = 255.0f / 768.0f;
    int zi[16];
    float zsum = 0.0f;
    #pragma unroll
    for (int e = 0; e < 16; ++e) {
        float u = fminf(fmaxf(v[e], -384.0f), 384.0f);
        float q = fminf(fmaxf(rintf((u + 384.0f) * inv_qs), 0.0f), 255.0f);
        zi[e] = (int)q - 128;
        zsum += (float)zi[e];
    }
    uint32_t pk[4];
    #pragma unroll
    for (int j = 0; j < 4; ++j)
        pk[j] = (uint32_t)(zi[4*j] & 0xff) | ((uint32_t)(zi[4*j+1] & 0xff) << 8) |
                ((uint32_t)(zi[4*j+2] & 0xff) << 16) | ((uint32_t)(zi[4*j+3] & 0xff) << 24);
    int8_t* oz = (mode ? g_zw : g_zx) + (size_t)row * PADDED + t * 16;
    *(uint4*)oz = make_uint4(pk[0], pk[1], pk[2], pk[3]);

    #pragma unroll
    for (int off = 16; off > 0; off >>= 1)
        zsum += __shfl_down_sync(0xffffffffu, zsum, off, 32);
    if ((t & 31) == 0) wsum[t >> 5] = zsum;
    __syncthreads();
    if (t == 0) {
        float S = 0.0f;
        #pragma unroll
        for (int i = 0; i < 8; ++i) S += wsum[i];
        float stat = kA * S;
        if (mode) g_beta[row] = stat + c2 + bias[row];
        else      g_alpha[row] = stat;
    }
}

// ============================================================================
// Kernel 2: warp-specialized hybrid GEMM, tile 128 x 192.
//   warps 0-7  : mma.sync (tensor pipe), cols 0..127
//   warps 8-15 : dp4a (fma pipe), cols 128..191, conflict-free interleaving
// 6 smem stages = 3 pair-slots; ONE __syncthreads per 2 chunks.
// ============================================================================
__device__ __forceinline__ void load_pair(uint32_t sb, const int8_t* Ag, const int8_t* Bg,
                                          int pair, int tid, int nbrows) {
    // chunks 2*pair, 2*pair+1 -> stages 2*(pair%3), 2*(pair%3)+1
    const int s0 = (pair % 3) * 2;
    const int k0 = pair * 2 * BK;
    #pragma unroll
    for (int j = 0; j < 5; ++j) {           // 2 x 1280 = 2560 segs / 512 thr
        int seg = tid + NTHREADS * j;
        int half = (seg >= 1280);
        int seg1 = seg - half * 1280;
        int s = s0 + half;
        int kh = k0 + half * BK;
        int r = seg1 >> 2, c = seg1 & 3;
        if (r < 128) {
            cpa16(sb + s * A_STAGE + SWZ64(r, c),
                  Ag + (size_t)r * K_DIM + kh + c * 16);
        } else {
            int br = r - 128;
            if (br < nbrows)
                cpa16(sb + SMEM_B_OFF + s * B_STAGE + SWZ64(br, c),
                      Bg + (size_t)br * K_DIM + kh + c * 16);
        }
    }
}

__global__ void __launch_bounds__(NTHREADS, 1)
hq_gemm(float* __restrict__ out, float k1) {
    extern __shared__ char smem[];
    const uint32_t sb = smem_u32(smem);
    const int tid = threadIdx.x;
    const int wid = tid >> 5, lane = tid & 31;

    const int m0 = blockIdx.y * BM;
    const int n0 = blockIdx.x * BN;
    const bool full = (n0 + BN <= N_COLS);       // last tile: 64 cols, tensor-only
    const int nbrows = full ? BN : (N_COLS - n0);

    const int8_t* Ag = g_zx + (size_t)m0 * K_DIM;
    const int8_t* Bg = g_zw + (size_t)n0 * K_DIM;

    // prologue: pair 0 in flight
    load_pair(sb, Ag, Bg, 0, tid, nbrows);
    asm volatile("cp.async.commit_group;" ::: "memory");

    if (wid < 8) {
        // ==================== tensor warps ====================
        const int warpM = wid & 3, warpN = wid >> 2;
        const bool active = full || (warpN == 0);

        const int arow = warpM * 32 + (lane & 7) + ((lane >> 3) & 1) * 8;
        const int acadd = (lane >> 4) & 1;
        const int axor = (arow >> 1) & 3;
        const int brow = warpN * 64 + (lane & 7) + ((lane >> 4) & 1) * 8;
        const int bcadd = (lane >> 3) & 1;
        const int bxor = (brow >> 1) & 3;

        int acc[64];
        #pragma unroll
        for (int i = 0; i < 64; ++i) acc[i] = 0;

        for (int p = 0; p < NPAIR; ++p) {
            if (p + 1 < NPAIR) {
                load_pair(sb, Ag, Bg, p + 1, tid, nbrows);
                asm volatile("cp.async.commit_group;" ::: "memory");
                asm volatile("cp.async.wait_group 1;" ::: "memory");
            } else {
                asm volatile("cp.async.wait_group 0;" ::: "memory");
            }
            __syncthreads();   // pair p visible to all; pair p-2's slot now free

            if (active) {
                #pragma unroll
                for (int h = 0; h < 2; ++h) {
                    uint32_t aS = sb + ((p % 3) * 2 + h) * A_STAGE;
                    uint32_t bS = sb + SMEM_B_OFF + ((p % 3) * 2 + h) * B_STAGE;
                    #pragma unroll
                    for (int kk = 0; kk < 2; ++kk) {
                        uint32_t af[8], bf[16];
                        #pragma unroll
                        for (int ma = 0; ma < 2; ++ma)
                            ldm4(aS + (uint32_t)(arow + ma * 16) * 64 +
                                     (uint32_t)(((2 * kk + acadd) ^ axor) << 4),
                                 af[4*ma], af[4*ma+1], af[4*ma+2], af[4*ma+3]);
                        #pragma unroll
                        for (int nb = 0; nb < 4; ++nb)
                            ldm4(bS + (uint32_t)(brow + nb * 16) * 64 +
                                     (uint32_t)(((2 * kk + bcadd) ^ bxor) << 4),
                                 bf[4*nb], bf[4*nb+1], bf[4*nb+2], bf[4*nb+3]);
                        #pragma unroll
                        for (int ma = 0; ma < 2; ++ma)
                            #pragma unroll
                            for (int na = 0; na < 8; ++na)
                                mma_s8(acc + (ma * 8 + na) * 4, af + 4 * ma,
                                       bf[(na >> 1) * 4 + (na & 1) * 2],
                                       bf[(na >> 1) * 4 + (na & 1) * 2 + 1]);
                    }
                }
            }
        }

        if (active) {
            #pragma unroll
            for (int ma = 0; ma < 2; ++ma) {
                int r0 = m0 + warpM * 32 + ma * 16 + (lane >> 2);
                float al0 = g_alpha[r0], al1 = g_alpha[r0 + 8];
                float* o0 = out + (size_t)r0 * N_COLS;
                float* o1 = out + (size_t)(r0 + 8) * N_COLS;
                #pragma unroll
                for (int na = 0; na < 8; ++na) {
                    int col = n0 + warpN * 64 + na * 8 + (lane & 3) * 2;
                    float b0 = g_beta[col], b1 = g_beta[col + 1];
                    const int* d = acc + (ma * 8 + na) * 4;
                    float2 p0, p1;
                    p0.x = fmaf(k1, (float)d[0], al0 + b0);
                    p0.y = fmaf(k1, (float)d[1], al0 + b1);
                    p1.x = fmaf(k1, (float)d[2], al1 + b0);
                    p1.y = fmaf(k1, (float)d[3], al1 + b1);
                    *(float2*)(o0 + col) = p0;
                    *(float2*)(o1 + col) = p1;
                }
            }
        }
    } else {
        // ==================== dp4a warps (interleaved, conflict-free) ======
        const int dwid = wid - 8;
        const int warpMd = dwid & 3;
        const int warpNd = dwid >> 2;
        const int dr0 = warpMd * 32 + (lane >> 2);       // rows dr0 + 8i
        const int db0 = BNT + warpNd * 32 + (lane & 3);  // tile cols db0 + 4j

        uint32_t aoffs[4], boffs[8];
        int akey[4], bkey[8];
        #pragma unroll
        for (int i = 0; i < 4; ++i) {
            int r = dr0 + 8 * i;
            aoffs[i] = (uint32_t)r << 6;
            akey[i] = (r >> 1) & 3;
        }
        #pragma unroll
        for (int j = 0; j < 8; ++j) {
            int r = db0 + 4 * j;
            boffs[j] = (uint32_t)r << 6;
            bkey[j] = (r >> 1) & 3;
        }

        int acc2[32];
        #pragma unroll
        for (int i = 0; i < 32; ++i) acc2[i] = 0;

        for (int p = 0; p < NPAIR; ++p) {
            if (p + 1 < NPAIR) {
                load_pair(sb, Ag, Bg, p + 1, tid, nbrows);
                asm volatile("cp.async.commit_group;" ::: "memory");
                asm volatile("cp.async.wait_group 1;" ::: "memory");
            } else {
                asm volatile("cp.async.wait_group 0;" ::: "memory");
            }
            __syncthreads();

            if (full) {
                #pragma unroll
                for (int h = 0; h < 2; ++h) {
                    uint32_t aS = sb + ((p % 3) * 2 + h) * A_STAGE;
                    uint32_t bS = sb + SMEM_B_OFF + ((p % 3) * 2 + h) * B_STAGE;
                    #pragma unroll
                    for (int kb = 0; kb < 4; ++kb) {
                        uint4 aw[4];
                        #pragma unroll
                        for (int i = 0; i < 4; ++i)
                            aw[i] = lds128(aS + aoffs[i] + (uint32_t)((kb ^ akey[i]) << 4));
                        #pragma unroll
                        for (int j = 0; j < 8; ++j) {
                            uint4 bw = lds128(bS + boffs[j] + (uint32_t)((kb ^ bkey[j]) << 4));
                            #pragma unroll
                            for (int i = 0; i < 4; ++i) {
                                int a0 = acc2[i * 8 + j];
                                a0 = dp4a_s(aw[i].x, bw.x, a0);
                                a0 = dp4a_s(aw[i].y, bw.y, a0);
                                a0 = dp4a_s(aw[i].z, bw.z, a0);
                                acc2[i * 8 + j] = dp4a_s(aw[i].w, bw.w, a0);
                            }
                        }
                    }
                }
            }
        }

        if (full) {
            #pragma unroll
            for (int i = 0; i < 4; ++i) {
                int row = m0 + dr0 + 8 * i;
                float al = g_alpha[row];
                float* orow = out + (size_t)row * N_COLS;
                #pragma unroll
                for (int j = 0; j < 8; ++j) {
                    int col = n0 + db0 + 4 * j;
                    orow[col] = fmaf(k1, (float)acc2[i * 8 + j], al + g_beta[col]);
                }
            }
        }
    }
}

// ============================================================================
extern "C" void kernel_launch(void* const* d_in, const int* in_sizes, int n_in,
                              void* d_out, int out_size) {
    const float* x = (const float*)d_in[0];
    const float* w = (const float*)d_in[1];
    const float* bias = (const float*)d_in[2];
    float* out = (float*)d_out;

    const float scale = 768.0f / 255.0f;
    const float cc = -384.0f + 128.0f * scale;        // = 384/255
    const float k1 = scale * scale / (float)PADDED;
    const float kA = scale * cc / (float)PADDED;
    const float c2 = cc * cc;

    hq_fwht_quant<<<M_ROWS + N_COLS, 256>>>(x, w, bias, kA, c2);

    static_assert(SMEM_TOTAL == 122880, "smem");
    cudaFuncSetAttribute(hq_gemm, cudaFuncAttributeMaxDynamicSharedMemorySize, SMEM_TOTAL);
    dim3 grid((N_COLS + BN - 1) / BN, M_ROWS / BM);   // 22 x 64
    hq_gemm<<<grid, NTHREADS, SMEM_TOTAL>>>(out, k1);
}

// round 10
// speedup vs baseline: 2.1447x; 1.1418x over previous
#include <cuda_runtime.h>
#include <cstdint>

#define IN_FEAT 3072
#define PADDED  4096
#define M_ROWS  8192
#define N_COLS  4096
#define K_DIM   4096

#define BM 128
#define BNT 128              // tensor columns (warps 0-7)
#define BND 96               // dp4a columns (warps 8-15)
#define BN (BNT + BND)       // 224
#define BK 64
#define NSTAGE 6             // 3 pair-slots x 2 chunks
#define NITER (K_DIM / BK)   // 64
#define NPAIR (NITER / 2)    // 32
#define NTHREADS 512

#define A_STAGE 8192                        // 128 rows x 64 B
#define B_STAGE (BN * BK)                   // 224 rows x 64 B = 14336
#define SMEM_B_OFF (NSTAGE * A_STAGE)       // 49152
#define SMEM_TOTAL (NSTAGE * (A_STAGE + B_STAGE))   // 135168
#define PAIR_SEGS (2 * (BM + BN) * 4)       // 2816 16B segments per pair

// -------- device scratch (static globals: no allocations allowed) ----------
__device__ int8_t g_zx[(size_t)M_ROWS * K_DIM];   // 32 MB
__device__ int8_t g_zw[(size_t)N_COLS * K_DIM];   // 16 MB
__device__ float  g_alpha[M_ROWS];
__device__ float  g_beta[N_COLS];

// -------- helpers -----------------------------------------------------------
__device__ __forceinline__ uint32_t smem_u32(const void* p) {
    uint32_t a;
    asm("{ .reg .u64 t; cvta.to.shared.u64 t, %1; cvt.u32.u64 %0, t; }"
        : "=r"(a) : "l"(p));
    return a;
}

__device__ __forceinline__ void cpa16(uint32_t sdst, const void* gsrc) {
    asm volatile("cp.async.cg.shared.global [%0], [%1], 16;" :: "r"(sdst), "l"(gsrc));
}

__device__ __forceinline__ void ldm4(uint32_t addr, uint32_t& r0, uint32_t& r1,
                                     uint32_t& r2, uint32_t& r3) {
    asm volatile("ldmatrix.sync.aligned.m8n8.x4.shared.b16 {%0,%1,%2,%3}, [%4];"
                 : "=r"(r0), "=r"(r1), "=r"(r2), "=r"(r3) : "r"(addr));
}

__device__ __forceinline__ void mma_s8(int* d, const uint32_t* a, uint32_t b0, uint32_t b1) {
    asm volatile(
        "mma.sync.aligned.m16n8k32.row.col.s32.s8.s8.s32 "
        "{%0,%1,%2,%3}, {%4,%5,%6,%7}, {%8,%9}, {%0,%1,%2,%3};"
        : "+r"(d[0]), "+r"(d[1]), "+r"(d[2]), "+r"(d[3])
        : "r"(a[0]), "r"(a[1]), "r"(a[2]), "r"(a[3]), "r"(b0), "r"(b1));
}

__device__ __forceinline__ uint4 lds128(uint32_t addr) {
    uint4 v;
    asm volatile("ld.shared.v4.u32 {%0,%1,%2,%3}, [%4];"
                 : "=r"(v.x), "=r"(v.y), "=r"(v.z), "=r"(v.w) : "r"(addr));
    return v;
}

__device__ __forceinline__ int dp4a_s(uint32_t a, uint32_t b, int c) {
    int d;
    asm("dp4a.s32.s32 %0, %1, %2, %3;" : "=r"(d) : "r"(a), "r"(b), "r"(c));
    return d;
}

// swizzle for 64-byte rows at 16B granules (cp.async / ldmatrix / LDS.128 safe)
#define SWZ64(row, c) (((uint32_t)(row) << 6) + ((((c) ^ (((row) >> 1) & 3)) & 3) << 4))

// ============================================================================
// Kernel 1: per-row pad -> FWHT(4096) -> quantize (z = q-128, int8) -> row sum
// ============================================================================
__global__ void __launch_bounds__(256)
hq_fwht_quant(const float* __restrict__ x, const float* __restrict__ w,
              const float* __restrict__ bias, float kA, float c2) {
    __shared__ float xch[PADDED];
    __shared__ float wsum[8];

    int row = blockIdx.x;
    int mode = (row >= M_ROWS);
    if (mode) row -= M_ROWS;
    const float* in = mode ? (w + (size_t)row * IN_FEAT) : (x + (size_t)row * IN_FEAT);
    const int t = threadIdx.x;

    float v[16];
    if (t < IN_FEAT / 16) {
        const float4* p = (const float4*)(in + t * 16);
        float4 a0 = p[0], a1 = p[1], a2 = p[2], a3 = p[3];
        v[0]=a0.x; v[1]=a0.y; v[2]=a0.z; v[3]=a0.w;
        v[4]=a1.x; v[5]=a1.y; v[6]=a1.z; v[7]=a1.w;
        v[8]=a2.x; v[9]=a2.y; v[10]=a2.z; v[11]=a2.w;
        v[12]=a3.x; v[13]=a3.y; v[14]=a3.z; v[15]=a3.w;
    } else {
        #pragma unroll
        for (int e = 0; e < 16; ++e) v[e] = 0.0f;
    }

    #pragma unroll
    for (int st = 1; st < 16; st <<= 1) {
        #pragma unroll
        for (int e = 0; e < 16; ++e)
            if (!(e & st)) {
                float a = v[e], b = v[e | st];
                v[e] = a + b;
                v[e | st] = a - b;
            }
    }
    #pragma unroll
    for (int b = 1; b <= 16; b <<= 1) {
        bool up = (t & b) != 0;
        #pragma unroll
        for (int e = 0; e < 16; ++e) {
            float o = __shfl_xor_sync(0xffffffffu, v[e], b, 32);
            v[e] = up ? (o - v[e]) : (v[e] + o);
        }
    }
    #pragma unroll
    for (int b = 32; b <= 128; b <<= 1) {
        __syncthreads();
        #pragma unroll
        for (int e = 0; e < 16; ++e) xch[e * 256 + t] = v[e];
        __syncthreads();
        int pt = t ^ b;
        bool up = (t & b) != 0;
        #pragma unroll
        for (int e = 0; e < 16; ++e) {
            float o = xch[e * 256 + pt];
            v[e] = up ? (o - v[e]) : (v[e] + o);
        }
    }

    const float inv_qs = 255.0f / 768.0f;
    int zi[16];
    float zsum = 0.0f;
    #pragma unroll
    for (int e = 0; e < 16; ++e) {
        float u = fminf(fmaxf(v[e], -384.0f), 384.0f);
        float q = fminf(fmaxf(rintf((u + 384.0f) * inv_qs), 0.0f), 255.0f);
        zi[e] = (int)q - 128;
        zsum += (float)zi[e];
    }
    uint32_t pk[4];
    #pragma unroll
    for (int j = 0; j < 4; ++j)
        pk[j] = (uint32_t)(zi[4*j] & 0xff) | ((uint32_t)(zi[4*j+1] & 0xff) << 8) |
                ((uint32_t)(zi[4*j+2] & 0xff) << 16) | ((uint32_t)(zi[4*j+3] & 0xff) << 24);
    int8_t* oz = (mode ? g_zw : g_zx) + (size_t)row * PADDED + t * 16;
    *(uint4*)oz = make_uint4(pk[0], pk[1], pk[2], pk[3]);

    #pragma unroll
    for (int off = 16; off > 0; off >>= 1)
        zsum += __shfl_down_sync(0xffffffffu, zsum, off, 32);
    if ((t & 31) == 0) wsum[t >> 5] = zsum;
    __syncthreads();
    if (t == 0) {
        float S = 0.0f;
        #pragma unroll
        for (int i = 0; i < 8; ++i) S += wsum[i];
        float stat = kA * S;
        if (mode) g_beta[row] = stat + c2 + bias[row];
        else      g_alpha[row] = stat;
    }
}

// ============================================================================
// Kernel 2: warp-specialized hybrid GEMM, tile 128 x 224.
//   warps 0-7  : mma.sync (tensor pipe), cols 0..127
//   warps 8-15 : dp4a (fma pipe), cols 128..223 (4 rows x 12 cols per thread)
// 6 smem stages = 3 pair-slots; ONE __syncthreads per 2 chunks.
// ============================================================================
__device__ __forceinline__ void load_pair(uint32_t sb, const int8_t* Ag, const int8_t* Bg,
                                          int pair, int tid, int nbrows) {
    const int s0 = (pair % 3) * 2;
    const int k0 = pair * 2 * BK;
    #pragma unroll
    for (int j = 0; j < 6; ++j) {           // PAIR_SEGS=2816 / 512 thr
        int seg = tid + NTHREADS * j;
        if (seg >= PAIR_SEGS) break;
        int half = (seg >= PAIR_SEGS / 2);
        int seg1 = seg - half * (PAIR_SEGS / 2);
        int s = s0 + half;
        int kh = k0 + half * BK;
        int r = seg1 >> 2, c = seg1 & 3;
        if (r < BM) {
            cpa16(sb + s * A_STAGE + SWZ64(r, c),
                  Ag + (size_t)r * K_DIM + kh + c * 16);
        } else {
            int br = r - BM;
            if (br < nbrows)
                cpa16(sb + SMEM_B_OFF + s * B_STAGE + SWZ64(br, c),
                      Bg + (size_t)br * K_DIM + kh + c * 16);
        }
    }
}

__global__ void __launch_bounds__(NTHREADS, 1)
hq_gemm(float* __restrict__ out, float k1) {
    extern __shared__ char smem[];
    const uint32_t sb = smem_u32(smem);
    const int tid = threadIdx.x;
    const int wid = tid >> 5, lane = tid & 31;

    const int m0 = blockIdx.y * BM;
    const int n0 = blockIdx.x * BN;
    const bool full = (n0 + BN <= N_COLS);       // last tile: 64 cols, tensor-only
    const int nbrows = full ? BN : (N_COLS - n0);

    const int8_t* Ag = g_zx + (size_t)m0 * K_DIM;
    const int8_t* Bg = g_zw + (size_t)n0 * K_DIM;

    load_pair(sb, Ag, Bg, 0, tid, nbrows);
    asm volatile("cp.async.commit_group;" ::: "memory");

    if (wid < 8) {
        // ==================== tensor warps ====================
        const int warpM = wid & 3, warpN = wid >> 2;
        const bool active = full || (warpN == 0);

        const int arow = warpM * 32 + (lane & 7) + ((lane >> 3) & 1) * 8;
        const int acadd = (lane >> 4) & 1;
        const int axor = (arow >> 1) & 3;
        const int brow = warpN * 64 + (lane & 7) + ((lane >> 4) & 1) * 8;
        const int bcadd = (lane >> 3) & 1;
        const int bxor = (brow >> 1) & 3;

        int acc[64];
        #pragma unroll
        for (int i = 0; i < 64; ++i) acc[i] = 0;

        for (int p = 0; p < NPAIR; ++p) {
            if (p + 1 < NPAIR) {
                load_pair(sb, Ag, Bg, p + 1, tid, nbrows);
                asm volatile("cp.async.commit_group;" ::: "memory");
                asm volatile("cp.async.wait_group 1;" ::: "memory");
            } else {
                asm volatile("cp.async.wait_group 0;" ::: "memory");
            }
            __syncthreads();   // pair p visible; pair p-2's slot now free

            if (active) {
                #pragma unroll
                for (int h = 0; h < 2; ++h) {
                    uint32_t aS = sb + ((p % 3) * 2 + h) * A_STAGE;
                    uint32_t bS = sb + SMEM_B_OFF + ((p % 3) * 2 + h) * B_STAGE;
                    #pragma unroll
                    for (int kk = 0; kk < 2; ++kk) {
                        uint32_t af[8], bf[16];
                        #pragma unroll
                        for (int ma = 0; ma < 2; ++ma)
                            ldm4(aS + (uint32_t)(arow + ma * 16) * 64 +
                                     (uint32_t)(((2 * kk + acadd) ^ axor) << 4),
                                 af[4*ma], af[4*ma+1], af[4*ma+2], af[4*ma+3]);
                        #pragma unroll
                        for (int nb = 0; nb < 4; ++nb)
                            ldm4(bS + (uint32_t)(brow + nb * 16) * 64 +
                                     (uint32_t)(((2 * kk + bcadd) ^ bxor) << 4),
                                 bf[4*nb], bf[4*nb+1], bf[4*nb+2], bf[4*nb+3]);
                        #pragma unroll
                        for (int ma = 0; ma < 2; ++ma)
                            #pragma unroll
                            for (int na = 0; na < 8; ++na)
                                mma_s8(acc + (ma * 8 + na) * 4, af + 4 * ma,
                                       bf[(na >> 1) * 4 + (na & 1) * 2],
                                       bf[(na >> 1) * 4 + (na & 1) * 2 + 1]);
                    }
                }
            }
        }

        if (active) {
            #pragma unroll
            for (int ma = 0; ma < 2; ++ma) {
                int r0 = m0 + warpM * 32 + ma * 16 + (lane >> 2);
                float al0 = g_alpha[r0], al1 = g_alpha[r0 + 8];
                float* o0 = out + (size_t)r0 * N_COLS;
                float* o1 = out + (size_t)(r0 + 8) * N_COLS;
                #pragma unroll
                for (int na = 0; na < 8; ++na) {
                    int col = n0 + warpN * 64 + na * 8 + (lane & 3) * 2;
                    float b0 = g_beta[col], b1 = g_beta[col + 1];
                    const int* d = acc + (ma * 8 + na) * 4;
                    float2 p0, p1;
                    p0.x = fmaf(k1, (float)d[0], al0 + b0);
                    p0.y = fmaf(k1, (float)d[1], al0 + b1);
                    p1.x = fmaf(k1, (float)d[2], al1 + b0);
                    p1.y = fmaf(k1, (float)d[3], al1 + b1);
                    *(float2*)(o0 + col) = p0;
                    *(float2*)(o1 + col) = p1;
                }
            }
        }
    } else {
        // ===== dp4a warps: 96 cols, 4 rows x 12 cols per thread =====
        const int dwid = wid - 8;
        const int warpMd = dwid & 3;                     // 4 groups x 32 rows
        const int warpNd = dwid >> 2;                    // 2 groups x 48 cols
        const int dr0 = warpMd * 32 + (lane >> 2);       // rows dr0 + 8i
        const int db0 = BNT + warpNd * 48 + (lane & 3);  // tile cols db0 + 4j

        int acc2[48];
        #pragma unroll
        for (int i = 0; i < 48; ++i) acc2[i] = 0;

        for (int p = 0; p < NPAIR; ++p) {
            if (p + 1 < NPAIR) {
                load_pair(sb, Ag, Bg, p + 1, tid, nbrows);
                asm volatile("cp.async.commit_group;" ::: "memory");
                asm volatile("cp.async.wait_group 1;" ::: "memory");
            } else {
                asm volatile("cp.async.wait_group 0;" ::: "memory");
            }
            __syncthreads();

            if (full) {
                #pragma unroll
                for (int h = 0; h < 2; ++h) {
                    uint32_t aS = sb + ((p % 3) * 2 + h) * A_STAGE;
                    uint32_t bS = sb + SMEM_B_OFF + ((p % 3) * 2 + h) * B_STAGE;
                    #pragma unroll
                    for (int kb = 0; kb < 4; ++kb) {
                        uint4 aw[4];
                        #pragma unroll
                        for (int i = 0; i < 4; ++i) {
                            int r = dr0 + 8 * i;
                            aw[i] = lds128(aS + ((uint32_t)r << 6) +
                                           (uint32_t)((kb ^ ((r >> 1) & 3)) << 4));
                        }
                        #pragma unroll
                        for (int j = 0; j < 12; ++j) {
                            int r = db0 + 4 * j;
                            uint4 bw = lds128(bS + ((uint32_t)r << 6) +
                                              (uint32_t)((kb ^ ((r >> 1) & 3)) << 4));
                            #pragma unroll
                            for (int i = 0; i < 4; ++i) {
                                int a0 = acc2[i * 12 + j];
                                a0 = dp4a_s(aw[i].x, bw.x, a0);
                                a0 = dp4a_s(aw[i].y, bw.y, a0);
                                a0 = dp4a_s(aw[i].z, bw.z, a0);
                                acc2[i * 12 + j] = dp4a_s(aw[i].w, bw.w, a0);
                            }
                        }
                    }
                }
            }
        }

        if (full) {
            #pragma unroll
            for (int i = 0; i < 4; ++i) {
                int row = m0 + dr0 + 8 * i;
                float al = g_alpha[row];
                float* orow = out + (size_t)row * N_COLS;
                #pragma unroll
                for (int j = 0; j < 12; ++j) {
                    int col = n0 + db0 + 4 * j;
                    orow[col] = fmaf(k1, (float)acc2[i * 12 + j], al + g_beta[col]);
                }
            }
        }
    }
}

// ============================================================================
extern "C" void kernel_launch(void* const* d_in, const int* in_sizes, int n_in,
                              void* d_out, int out_size) {
    const float* x = (const float*)d_in[0];
    const float* w = (const float*)d_in[1];
    const float* bias = (const float*)d_in[2];
    float* out = (float*)d_out;

    const float scale = 768.0f / 255.0f;
    const float cc = -384.0f + 128.0f * scale;        // = 384/255
    const float k1 = scale * scale / (float)PADDED;
    const float kA = scale * cc / (float)PADDED;
    const float c2 = cc * cc;

    hq_fwht_quant<<<M_ROWS + N_COLS, 256>>>(x, w, bias, kA, c2);

    static_assert(SMEM_TOTAL == 135168, "smem");
    cudaFuncSetAttribute(hq_gemm, cudaFuncAttributeMaxDynamicSharedMemorySize, SMEM_TOTAL);
    dim3 grid((N_COLS + BN - 1) / BN, M_ROWS / BM);   // 19 x 64
    hq_gemm<<<grid, NTHREADS, SMEM_TOTAL>>>(out, k1);
}

// round 11
// speedup vs baseline: 2.2350x; 1.0421x over previous
#include <cuda_runtime.h>
#include <cstdint>

#define IN_FEAT 3072
#define PADDED  4096
#define M_ROWS  8192
#define N_COLS  4096
#define K_DIM   4096

#define BM 128
#define BNT 128              // tensor columns (warps 0-7)
#define BND 128              // dp4a columns (warps 8-15)
#define BN (BNT + BND)       // 256 -- divides N_COLS exactly
#define BK 64
#define NSTAGE 6             // 3 pair-slots x 2 chunks
#define NITER (K_DIM / BK)   // 64
#define NPAIR (NITER / 2)    // 32
#define NTHREADS 512

#define A_STAGE 8192                        // 128 rows x 64 B
#define B_STAGE (BN * BK)                   // 256 rows x 64 B = 16384
#define SMEM_B_OFF (NSTAGE * A_STAGE)       // 49152
#define SMEM_TOTAL (NSTAGE * (A_STAGE + B_STAGE))   // 147456
#define PAIR_SEGS (2 * (BM + BN) * 4)       // 3072 16B segments per pair

// -------- device scratch (static globals: no allocations allowed) ----------
__device__ int8_t g_zx[(size_t)M_ROWS * K_DIM];   // 32 MB
__device__ int8_t g_zw[(size_t)N_COLS * K_DIM];   // 16 MB
__device__ float  g_alpha[M_ROWS];
__device__ float  g_beta[N_COLS];

// -------- helpers -----------------------------------------------------------
__device__ __forceinline__ uint32_t smem_u32(const void* p) {
    uint32_t a;
    asm("{ .reg .u64 t; cvta.to.shared.u64 t, %1; cvt.u32.u64 %0, t; }"
        : "=r"(a) : "l"(p));
    return a;
}

__device__ __forceinline__ void cpa16(uint32_t sdst, const void* gsrc) {
    asm volatile("cp.async.cg.shared.global [%0], [%1], 16;" :: "r"(sdst), "l"(gsrc));
}

__device__ __forceinline__ void ldm4(uint32_t addr, uint32_t& r0, uint32_t& r1,
                                     uint32_t& r2, uint32_t& r3) {
    asm volatile("ldmatrix.sync.aligned.m8n8.x4.shared.b16 {%0,%1,%2,%3}, [%4];"
                 : "=r"(r0), "=r"(r1), "=r"(r2), "=r"(r3) : "r"(addr));
}

__device__ __forceinline__ void mma_s8(int* d, const uint32_t* a, uint32_t b0, uint32_t b1) {
    asm volatile(
        "mma.sync.aligned.m16n8k32.row.col.s32.s8.s8.s32 "
        "{%0,%1,%2,%3}, {%4,%5,%6,%7}, {%8,%9}, {%0,%1,%2,%3};"
        : "+r"(d[0]), "+r"(d[1]), "+r"(d[2]), "+r"(d[3])
        : "r"(a[0]), "r"(a[1]), "r"(a[2]), "r"(a[3]), "r"(b0), "r"(b1));
}

__device__ __forceinline__ uint4 lds128(uint32_t addr) {
    uint4 v;
    asm volatile("ld.shared.v4.u32 {%0,%1,%2,%3}, [%4];"
                 : "=r"(v.x), "=r"(v.y), "=r"(v.z), "=r"(v.w) : "r"(addr));
    return v;
}

__device__ __forceinline__ int dp4a_s(uint32_t a, uint32_t b, int c) {
    int d;
    asm("dp4a.s32.s32 %0, %1, %2, %3;" : "=r"(d) : "r"(a), "r"(b), "r"(c));
    return d;
}

// swizzle for 64-byte rows at 16B granules (cp.async / ldmatrix / LDS.128 safe)
#define SWZ64(row, c) (((uint32_t)(row) << 6) + ((((c) ^ (((row) >> 1) & 3)) & 3) << 4))

// ============================================================================
// Kernel 1: per-row pad -> FWHT(4096) -> quantize (z = q-128, int8) -> row sum
// ============================================================================
__global__ void __launch_bounds__(256)
hq_fwht_quant(const float* __restrict__ x, const float* __restrict__ w,
              const float* __restrict__ bias, float kA, float c2) {
    __shared__ float xch[PADDED];
    __shared__ float wsum[8];

    int row = blockIdx.x;
    int mode = (row >= M_ROWS);
    if (mode) row -= M_ROWS;
    const float* in = mode ? (w + (size_t)row * IN_FEAT) : (x + (size_t)row * IN_FEAT);
    const int t = threadIdx.x;

    float v[16];
    if (t < IN_FEAT / 16) {
        const float4* p = (const float4*)(in + t * 16);
        float4 a0 = p[0], a1 = p[1], a2 = p[2], a3 = p[3];
        v[0]=a0.x; v[1]=a0.y; v[2]=a0.z; v[3]=a0.w;
        v[4]=a1.x; v[5]=a1.y; v[6]=a1.z; v[7]=a1.w;
        v[8]=a2.x; v[9]=a2.y; v[10]=a2.z; v[11]=a2.w;
        v[12]=a3.x; v[13]=a3.y; v[14]=a3.z; v[15]=a3.w;
    } else {
        #pragma unroll
        for (int e = 0; e < 16; ++e) v[e] = 0.0f;
    }

    #pragma unroll
    for (int st = 1; st < 16; st <<= 1) {
        #pragma unroll
        for (int e = 0; e < 16; ++e)
            if (!(e & st)) {
                float a = v[e], b = v[e | st];
                v[e] = a + b;
                v[e | st] = a - b;
            }
    }
    #pragma unroll
    for (int b = 1; b <= 16; b <<= 1) {
        bool up = (t & b) != 0;
        #pragma unroll
        for (int e = 0; e < 16; ++e) {
            float o = __shfl_xor_sync(0xffffffffu, v[e], b, 32);
            v[e] = up ? (o - v[e]) : (v[e] + o);
        }
    }
    #pragma unroll
    for (int b = 32; b <= 128; b <<= 1) {
        __syncthreads();
        #pragma unroll
        for (int e = 0; e < 16; ++e) xch[e * 256 + t] = v[e];
        __syncthreads();
        int pt = t ^ b;
        bool up = (t & b) != 0;
        #pragma unroll
        for (int e = 0; e < 16; ++e) {
            float o = xch[e * 256 + pt];
            v[e] = up ? (o - v[e]) : (v[e] + o);
        }
    }

    const float inv_qs = 255.0f / 768.0f;
    int zi[16];
    float zsum = 0.0f;
    #pragma unroll
    for (int e = 0; e < 16; ++e) {
        float u = fminf(fmaxf(v[e], -384.0f), 384.0f);
        float q = fminf(fmaxf(rintf((u + 384.0f) * inv_qs), 0.0f), 255.0f);
        zi[e] = (int)q - 128;
        zsum += (float)zi[e];
    }
    uint32_t pk[4];
    #pragma unroll
    for (int j = 0; j < 4; ++j)
        pk[j] = (uint32_t)(zi[4*j] & 0xff) | ((uint32_t)(zi[4*j+1] & 0xff) << 8) |
                ((uint32_t)(zi[4*j+2] & 0xff) << 16) | ((uint32_t)(zi[4*j+3] & 0xff) << 24);
    int8_t* oz = (mode ? g_zw : g_zx) + (size_t)row * PADDED + t * 16;
    *(uint4*)oz = make_uint4(pk[0], pk[1], pk[2], pk[3]);

    #pragma unroll
    for (int off = 16; off > 0; off >>= 1)
        zsum += __shfl_down_sync(0xffffffffu, zsum, off, 32);
    if ((t & 31) == 0) wsum[t >> 5] = zsum;
    __syncthreads();
    if (t == 0) {
        float S = 0.0f;
        #pragma unroll
        for (int i = 0; i < 8; ++i) S += wsum[i];
        float stat = kA * S;
        if (mode) g_beta[row] = stat + c2 + bias[row];
        else      g_alpha[row] = stat;
    }
}

// ============================================================================
// Kernel 2: warp-specialized hybrid GEMM, tile 128 x 256 (BN | N: no remainder)
//   warps 0-7  : mma.sync (tensor pipe), cols 0..127
//   warps 8-15 : dp4a (fma pipe), cols 128..255 (4 rows x 16 cols per thread)
// 6 smem stages = 3 pair-slots; ONE __syncthreads per 2 chunks.
// ============================================================================
__device__ __forceinline__ void load_pair(uint32_t sb, const int8_t* Ag, const int8_t* Bg,
                                          int pair, int tid) {
    const int s0 = (pair % 3) * 2;
    const int k0 = pair * 2 * BK;
    #pragma unroll
    for (int j = 0; j < PAIR_SEGS / NTHREADS; ++j) {   // 3072/512 = 6
        int seg = tid + NTHREADS * j;
        int half = (seg >= PAIR_SEGS / 2);
        int seg1 = seg - half * (PAIR_SEGS / 2);
        int s = s0 + half;
        int kh = k0 + half * BK;
        int r = seg1 >> 2, c = seg1 & 3;
        if (r < BM) {
            cpa16(sb + s * A_STAGE + SWZ64(r, c),
                  Ag + (size_t)r * K_DIM + kh + c * 16);
        } else {
            int br = r - BM;
            cpa16(sb + SMEM_B_OFF + s * B_STAGE + SWZ64(br, c),
                  Bg + (size_t)br * K_DIM + kh + c * 16);
        }
    }
}

__global__ void __launch_bounds__(NTHREADS, 1)
hq_gemm(float* __restrict__ out, float k1) {
    extern __shared__ char smem[];
    const uint32_t sb = smem_u32(smem);
    const int tid = threadIdx.x;
    const int wid = tid >> 5, lane = tid & 31;

    const int m0 = blockIdx.y * BM;
    const int n0 = blockIdx.x * BN;

    const int8_t* Ag = g_zx + (size_t)m0 * K_DIM;
    const int8_t* Bg = g_zw + (size_t)n0 * K_DIM;

    load_pair(sb, Ag, Bg, 0, tid);
    asm volatile("cp.async.commit_group;" ::: "memory");

    if (wid < 8) {
        // ==================== tensor warps ====================
        const int warpM = wid & 3, warpN = wid >> 2;

        const int arow = warpM * 32 + (lane & 7) + ((lane >> 3) & 1) * 8;
        const int acadd = (lane >> 4) & 1;
        const int axor = (arow >> 1) & 3;
        const int brow = warpN * 64 + (lane & 7) + ((lane >> 4) & 1) * 8;
        const int bcadd = (lane >> 3) & 1;
        const int bxor = (brow >> 1) & 3;

        int acc[64];
        #pragma unroll
        for (int i = 0; i < 64; ++i) acc[i] = 0;

        for (int p = 0; p < NPAIR; ++p) {
            if (p + 1 < NPAIR) {
                load_pair(sb, Ag, Bg, p + 1, tid);
                asm volatile("cp.async.commit_group;" ::: "memory");
                asm volatile("cp.async.wait_group 1;" ::: "memory");
            } else {
                asm volatile("cp.async.wait_group 0;" ::: "memory");
            }
            __syncthreads();   // pair p visible; pair p-2's slot now free

            #pragma unroll
            for (int h = 0; h < 2; ++h) {
                uint32_t aS = sb + ((p % 3) * 2 + h) * A_STAGE;
                uint32_t bS = sb + SMEM_B_OFF + ((p % 3) * 2 + h) * B_STAGE;
                #pragma unroll
                for (int kk = 0; kk < 2; ++kk) {
                    uint32_t af[8], bf[16];
                    #pragma unroll
                    for (int ma = 0; ma < 2; ++ma)
                        ldm4(aS + (uint32_t)(arow + ma * 16) * 64 +
                                 (uint32_t)(((2 * kk + acadd) ^ axor) << 4),
                             af[4*ma], af[4*ma+1], af[4*ma+2], af[4*ma+3]);
                    #pragma unroll
                    for (int nb = 0; nb < 4; ++nb)
                        ldm4(bS + (uint32_t)(brow + nb * 16) * 64 +
                                 (uint32_t)(((2 * kk + bcadd) ^ bxor) << 4),
                             bf[4*nb], bf[4*nb+1], bf[4*nb+2], bf[4*nb+3]);
                    #pragma unroll
                    for (int ma = 0; ma < 2; ++ma)
                        #pragma unroll
                        for (int na = 0; na < 8; ++na)
                            mma_s8(acc + (ma * 8 + na) * 4, af + 4 * ma,
                                   bf[(na >> 1) * 4 + (na & 1) * 2],
                                   bf[(na >> 1) * 4 + (na & 1) * 2 + 1]);
                }
            }
        }

        #pragma unroll
        for (int ma = 0; ma < 2; ++ma) {
            int r0 = m0 + warpM * 32 + ma * 16 + (lane >> 2);
            float al0 = g_alpha[r0], al1 = g_alpha[r0 + 8];
            float* o0 = out + (size_t)r0 * N_COLS;
            float* o1 = out + (size_t)(r0 + 8) * N_COLS;
            #pragma unroll
            for (int na = 0; na < 8; ++na) {
                int col = n0 + warpN * 64 + na * 8 + (lane & 3) * 2;
                float b0 = g_beta[col], b1 = g_beta[col + 1];
                const int* d = acc + (ma * 8 + na) * 4;
                float2 p0, p1;
                p0.x = fmaf(k1, (float)d[0], al0 + b0);
                p0.y = fmaf(k1, (float)d[1], al0 + b1);
                p1.x = fmaf(k1, (float)d[2], al1 + b0);
                p1.y = fmaf(k1, (float)d[3], al1 + b1);
                *(float2*)(o0 + col) = p0;
                *(float2*)(o1 + col) = p1;
            }
        }
    } else {
        // ===== dp4a warps: 128 cols, 4 rows x 16 cols per thread =====
        const int dwid = wid - 8;
        const int warpMd = dwid & 3;                     // 4 groups x 32 rows
        const int warpNd = dwid >> 2;                    // 2 groups x 64 cols
        const int dr0 = warpMd * 32 + (lane >> 2);       // rows dr0 + 8i
        const int db0 = BNT + warpNd * 64 + (lane & 3);  // tile cols db0 + 4j

        int acc2[64];
        #pragma unroll
        for (int i = 0; i < 64; ++i) acc2[i] = 0;

        for (int p = 0; p < NPAIR; ++p) {
            if (p + 1 < NPAIR) {
                load_pair(sb, Ag, Bg, p + 1, tid);
                asm volatile("cp.async.commit_group;" ::: "memory");
                asm volatile("cp.async.wait_group 1;" ::: "memory");
            } else {
                asm volatile("cp.async.wait_group 0;" ::: "memory");
            }
            __syncthreads();

            #pragma unroll
            for (int h = 0; h < 2; ++h) {
                uint32_t aS = sb + ((p % 3) * 2 + h) * A_STAGE;
                uint32_t bS = sb + SMEM_B_OFF + ((p % 3) * 2 + h) * B_STAGE;
                #pragma unroll
                for (int kb = 0; kb < 4; ++kb) {
                    uint4 aw[4];
                    #pragma unroll
                    for (int i = 0; i < 4; ++i) {
                        int r = dr0 + 8 * i;
                        aw[i] = lds128(aS + ((uint32_t)r << 6) +
                                       (uint32_t)((kb ^ ((r >> 1) & 3)) << 4));
                    }
                    #pragma unroll
                    for (int j = 0; j < 16; ++j) {
                        int r = db0 + 4 * j;
                        uint4 bw = lds128(bS + ((uint32_t)r << 6) +
                                          (uint32_t)((kb ^ ((r >> 1) & 3)) << 4));
                        #pragma unroll
                        for (int i = 0; i < 4; ++i) {
                            int a0 = acc2[i * 16 + j];
                            a0 = dp4a_s(aw[i].x, bw.x, a0);
                            a0 = dp4a_s(aw[i].y, bw.y, a0);
                            a0 = dp4a_s(aw[i].z, bw.z, a0);
                            acc2[i * 16 + j] = dp4a_s(aw[i].w, bw.w, a0);
                        }
                    }
                }
            }
        }

        #pragma unroll
        for (int i = 0; i < 4; ++i) {
            int row = m0 + dr0 + 8 * i;
            float al = g_alpha[row];
            float* orow = out + (size_t)row * N_COLS;
            #pragma unroll
            for (int j = 0; j < 16; ++j) {
                int col = n0 + db0 + 4 * j;
                orow[col] = fmaf(k1, (float)acc2[i * 16 + j], al + g_beta[col]);
            }
        }
    }
}

// ============================================================================
extern "C" void kernel_launch(void* const* d_in, const int* in_sizes, int n_in,
                              void* d_out, int out_size) {
    const float* x = (const float*)d_in[0];
    const float* w = (const float*)d_in[1];
    const float* bias = (const float*)d_in[2];
    float* out = (float*)d_out;

    const float scale = 768.0f / 255.0f;
    const float cc = -384.0f + 128.0f * scale;        // = 384/255
    const float k1 = scale * scale / (float)PADDED;
    const float kA = scale * cc / (float)PADDED;
    const float c2 = cc * cc;

    hq_fwht_quant<<<M_ROWS + N_COLS, 256>>>(x, w, bias, kA, c2);

    static_assert(SMEM_TOTAL == 147456, "smem");
    cudaFuncSetAttribute(hq_gemm, cudaFuncAttributeMaxDynamicSharedMemorySize, SMEM_TOTAL);
    dim3 grid(N_COLS / BN, M_ROWS / BM);              // 16 x 64
    hq_gemm<<<grid, NTHREADS, SMEM_TOTAL>>>(out, k1);
}